// round 9
// baseline (speedup 1.0000x reference)
#include <cuda_runtime.h>

#define N_NODES 100000
#define E_MAX   1600000
#define HID 128
#define NUM_IN 32
#define IN_DIM 71
#define LN_EPS 1e-5f
#define NB_SCAN ((N_NODES + 255) / 256)   // 391

// ---- packed fp32x2 helpers (sm_103a FFMA2: full fp32 precision, 2x rate) ----
#define FMA2(acc, a, b) \
    asm("fma.rn.f32x2 %0, %1, %2, %0;" : "+l"(acc) : "l"(a), "l"(b))
#define PACK_DUP(dst, x) do { \
    unsigned int _u = __float_as_uint(x); \
    asm("mov.b64 %0, {%1,%1};" : "=l"(dst) : "r"(_u)); } while (0)
#define PACK2(dst, lo, hi) \
    asm("mov.b64 %0, {%1,%2};" : "=l"(dst) : "r"(__float_as_uint(lo)), "r"(__float_as_uint(hi)))
#define UNPACK2(lo, hi, v) do { \
    unsigned int _l, _h; \
    asm("mov.b64 {%0,%1}, %2;" : "=r"(_l), "=r"(_h) : "l"(v)); \
    lo = __uint_as_float(_l); hi = __uint_as_float(_h); } while (0)

typedef unsigned long long u64;

// ---- scratch (device globals; no allocation allowed) ----
__device__ __align__(16) float g_xA[N_NODES * HID];   // ping
__device__ __align__(16) float g_xB[N_NODES * HID];   // pong
__device__ int g_deg[N_NODES];
__device__ int g_rowptr[N_NODES + 1];
__device__ int g_cursor[N_NODES];
__device__ int g_csr[E_MAX];                          // src ids grouped by dst
__device__ int g_bsum[512];
__device__ int g_boff[512];

// ------------------------------------------------------------------
// CSR build: zero deg -> histogram -> 2-level exclusive scan -> fill
// ------------------------------------------------------------------
__global__ void zero_deg_kernel() {
    int i = blockIdx.x * blockDim.x + threadIdx.x;
    if (i < N_NODES) g_deg[i] = 0;
}

__global__ void hist_kernel(const int* __restrict__ dst, int E) {
    int i = blockIdx.x * blockDim.x + threadIdx.x;
    if (i < E) atomicAdd(&g_deg[dst[i]], 1);
}

__global__ __launch_bounds__(256) void scan1_kernel() {
    int tid = threadIdx.x;
    int lane = tid & 31, wid = tid >> 5;
    int i = blockIdx.x * 256 + tid;
    int v = (i < N_NODES) ? g_deg[i] : 0;
    int x = v;
#pragma unroll
    for (int o = 1; o < 32; o <<= 1) {
        int y = __shfl_up_sync(0xffffffffu, x, o);
        if (lane >= o) x += y;
    }
    __shared__ int wsum[8];
    if (lane == 31) wsum[wid] = x;
    __syncthreads();
    if (tid == 0) {
        int run = 0;
#pragma unroll
        for (int w = 0; w < 8; w++) { int t = wsum[w]; wsum[w] = run; run += t; }
        g_bsum[blockIdx.x] = run;
    }
    __syncthreads();
    int excl = x - v + wsum[wid];
    if (i < N_NODES) g_rowptr[i] = excl;
}

__global__ __launch_bounds__(512) void scan2_kernel() {
    __shared__ int s[512];
    int tid = threadIdx.x;
    int v = (tid < NB_SCAN) ? g_bsum[tid] : 0;
    s[tid] = v;
    __syncthreads();
    for (int o = 1; o < 512; o <<= 1) {
        int t = (tid >= o) ? s[tid - o] : 0;
        __syncthreads();
        s[tid] += t;
        __syncthreads();
    }
    if (tid < NB_SCAN) g_boff[tid] = s[tid] - v;   // exclusive
}

__global__ void scan3_kernel(int E) {
    int i = blockIdx.x * blockDim.x + threadIdx.x;
    if (i < N_NODES) {
        int v = g_rowptr[i] + g_boff[blockIdx.x];
        g_rowptr[i] = v;
        g_cursor[i] = v;
    }
    if (i == 0) g_rowptr[N_NODES] = E;
}

__global__ void fill_kernel(const int* __restrict__ src, const int* __restrict__ dst, int E) {
    int i = blockIdx.x * blockDim.x + threadIdx.x;
    if (i < E) {
        int d = dst[i];
        int pos = atomicAdd(&g_cursor[d], 1);
        g_csr[pos] = src[i];
    }
}

// ------------------------------------------------------------------
// input: x = relu(concat(x_num, emb lookups) @ w_in + b_in)
// ------------------------------------------------------------------
__global__ __launch_bounds__(128) void input_kernel(
    const float* __restrict__ x_num, const int* __restrict__ x_cat,
    const float* __restrict__ emb0, const float* __restrict__ emb1,
    const float* __restrict__ emb2, const float* __restrict__ emb3,
    const float* __restrict__ w_in, const float* __restrict__ b_in,
    float* __restrict__ xout)
{
    __shared__ float ws[IN_DIM * HID];       // 36352 B
    __shared__ float insT[IN_DIM * 32];      // k-major: insT[k*32 + n], 9088 B
    int tid = threadIdx.x;
    for (int i = tid; i < IN_DIM * HID; i += 128) ws[i] = w_in[i];

    int node0 = blockIdx.x * 32;
    for (int i = tid; i < 32 * NUM_IN; i += 128) {
        int n = i / NUM_IN, k = i % NUM_IN;
        int node = node0 + n;
        insT[k * 32 + n] = (node < N_NODES) ? x_num[node * NUM_IN + k] : 0.f;
    }
    for (int i = tid; i < 32 * 39; i += 128) {
        int n = i / 39, j = i % 39;
        int node = node0 + n;
        float v = 0.f;
        if (node < N_NODES) {
            if (j < 10)      v = emb0[x_cat[node * 4 + 0] * 10 + j];
            else if (j < 16) v = emb1[x_cat[node * 4 + 1] * 6 + (j - 10)];
            else if (j < 21) v = emb2[x_cat[node * 4 + 2] * 5 + (j - 16)];
            else             v = emb3[x_cat[node * 4 + 3] * 18 + (j - 21)];
        }
        insT[(NUM_IN + j) * 32 + n] = v;
    }
    __syncthreads();

    u64 acc2[16];
#pragma unroll
    for (int p = 0; p < 16; p++) acc2[p] = 0ull;

    for (int k = 0; k < IN_DIM; k++) {
        float w = ws[k * HID + tid];
        u64 w2; PACK_DUP(w2, w);
        const u64* ip = reinterpret_cast<const u64*>(&insT[k * 32]);
#pragma unroll
        for (int p = 0; p < 16; p++) {
            u64 in2 = ip[p];
            FMA2(acc2[p], w2, in2);
        }
    }
    float b = b_in[tid];
#pragma unroll
    for (int p = 0; p < 16; p++) {
        float lo, hi;
        UNPACK2(lo, hi, acc2[p]);
        int n0 = node0 + 2 * p;
        if (n0 < N_NODES)     xout[(size_t)n0 * HID + tid]       = fmaxf(lo + b, 0.f);
        if (n0 + 1 < N_NODES) xout[(size_t)(n0 + 1) * HID + tid] = fmaxf(hi + b, 0.f);
    }
}

// ------------------------------------------------------------------
// SAGE update (gather + GEMM + LN fused), ping-pong safe.
// BM=64, BN=128, BK=32, 256 threads (16x16).
// Thread (tx,ty): rows ty*4..+3, cols {4tx..4tx+3} (lo) and {64+4tx..+3} (hi).
// B pre-paired in smem as u64 (lo=col c, hi=col c+64): inner loop has
// ZERO pack instructions on the B side (2x LDS.128 per k).
// ------------------------------------------------------------------
__global__ __launch_bounds__(256) void sage_kernel(
    const float* __restrict__ xin, float* __restrict__ xout,
    const float* __restrict__ wl, const float* __restrict__ bl,
    const float* __restrict__ wr,
    const float* __restrict__ gam, const float* __restrict__ bet)
{
    __shared__ float sMean[64 * 128];  // 32 KB
    __shared__ float As[64 * 32];      // 8 KB (xin tile for kt>=4)
    __shared__ u64   Bs2[32 * 64];     // 16 KB: Bs2[k*64+c] = (w[k][c], w[k][c+64])

    int tid = threadIdx.x;
    int row0 = blockIdx.x * 64;
    int warp = tid >> 5, lane = tid & 31;
    const float4* x4 = reinterpret_cast<const float4*>(xin);

    // ---- phase 1: gather mean (warp per row, 8 rows per warp) ----
#pragma unroll 1
    for (int j = 0; j < 8; j++) {
        int r = warp * 8 + j;
        int row = row0 + r;
        int beg = 0, end = 0;
        if (row < N_NODES) { beg = g_rowptr[row]; end = g_rowptr[row + 1]; }
        float4 a0 = make_float4(0.f, 0.f, 0.f, 0.f);
        float4 a1 = a0, a2 = a0, a3 = a0;
        int e = beg;
        for (; e + 4 <= end; e += 4) {
            int s0 = __ldg(&g_csr[e]);
            int s1 = __ldg(&g_csr[e + 1]);
            int s2 = __ldg(&g_csr[e + 2]);
            int s3 = __ldg(&g_csr[e + 3]);
            float4 v0 = x4[(size_t)s0 * 32 + lane];
            float4 v1 = x4[(size_t)s1 * 32 + lane];
            float4 v2 = x4[(size_t)s2 * 32 + lane];
            float4 v3 = x4[(size_t)s3 * 32 + lane];
            a0.x += v0.x; a0.y += v0.y; a0.z += v0.z; a0.w += v0.w;
            a1.x += v1.x; a1.y += v1.y; a1.z += v1.z; a1.w += v1.w;
            a2.x += v2.x; a2.y += v2.y; a2.z += v2.z; a2.w += v2.w;
            a3.x += v3.x; a3.y += v3.y; a3.z += v3.z; a3.w += v3.w;
        }
        for (; e < end; e++) {
            int s = __ldg(&g_csr[e]);
            float4 v = x4[(size_t)s * 32 + lane];
            a0.x += v.x; a0.y += v.y; a0.z += v.z; a0.w += v.w;
        }
        float inv = 1.f / fmaxf((float)(end - beg), 1.f);
        float4 m;
        m.x = (a0.x + a1.x + a2.x + a3.x) * inv;
        m.y = (a0.y + a1.y + a2.y + a3.y) * inv;
        m.z = (a0.z + a1.z + a2.z + a3.z) * inv;
        m.w = (a0.w + a1.w + a2.w + a3.w) * inv;
        reinterpret_cast<float4*>(sMean)[r * 32 + lane] = m;
    }
    __syncthreads();

    // ---- phase 2: GEMM ----
    int tx = tid & 15, ty = tid >> 4;
    u64 acc2[4][4];   // [row i][j]: lo = col 4tx+j, hi = col 64+4tx+j
#pragma unroll
    for (int i = 0; i < 4; i++)
#pragma unroll
        for (int j = 0; j < 4; j++) acc2[i][j] = 0ull;

#pragma unroll 1
    for (int kt = 0; kt < 8; kt++) {
        int kg0 = kt * 32;
        // stage xin tile for kg>=128 (mean tile already resident in sMean)
        if (kt >= 4) {
#pragma unroll
            for (int p = 0; p < 8; p++) {
                int idx = tid + p * 256;
                int r = idx >> 5, k = idx & 31;
                int row = row0 + r;
                As[r * 32 + k] = (row < N_NODES)
                    ? xin[(size_t)row * HID + (kg0 - 128 + k)] : 0.f;
            }
        }
        // stage B tile pre-paired: Bs2[k][c] = (w[kg][c], w[kg][c+64])
#pragma unroll
        for (int p = 0; p < 8; p++) {
            int idx = tid + p * 256;     // 0..2047
            int k = idx >> 6, c = idx & 63;
            int kg = kg0 + k;
            const float* wsrc = (kg < 128) ? (wl + kg * 128) : (wr + (kg - 128) * 128);
            float lo = wsrc[c];
            float hi = wsrc[c + 64];
            u64 pr; PACK2(pr, lo, hi);
            Bs2[k * 64 + c] = pr;
        }
        __syncthreads();

        const float* Abase = (kt < 4) ? (sMean + kg0) : As;
        int astr = (kt < 4) ? 128 : 32;
#pragma unroll
        for (int k = 0; k < 32; k++) {
            u64 a2[4];
#pragma unroll
            for (int i = 0; i < 4; i++) {
                float a = Abase[(ty * 4 + i) * astr + k];
                PACK_DUP(a2[i], a);
            }
            ulonglong2 q0 = *reinterpret_cast<const ulonglong2*>(&Bs2[k * 64 + tx * 4]);
            ulonglong2 q1 = *reinterpret_cast<const ulonglong2*>(&Bs2[k * 64 + tx * 4 + 2]);
            u64 b2[4] = {q0.x, q0.y, q1.x, q1.y};
#pragma unroll
            for (int i = 0; i < 4; i++)
#pragma unroll
                for (int j = 0; j < 4; j++)
                    FMA2(acc2[i][j], a2[i], b2[j]);
        }
        __syncthreads();
    }

    // epilogue: +bias, LayerNorm (16-lane shfl reduce), relu, residual
    int c0 = tx * 4;          // lo cols c0..c0+3
    int c1 = 64 + tx * 4;     // hi cols c1..c1+3
    float bl0[4], gm0[4], be0[4], bl1[4], gm1[4], be1[4];
#pragma unroll
    for (int j = 0; j < 4; j++) {
        bl0[j] = bl[c0 + j];  gm0[j] = gam[c0 + j];  be0[j] = bet[c0 + j];
        bl1[j] = bl[c1 + j];  gm1[j] = gam[c1 + j];  be1[j] = bet[c1 + j];
    }
#pragma unroll
    for (int i = 0; i < 4; i++) {
        int row = row0 + ty * 4 + i;
        float v[8];   // v[0..3] lo cols, v[4..7] hi cols
#pragma unroll
        for (int j = 0; j < 4; j++) {
            UNPACK2(v[j], v[4 + j], acc2[i][j]);
            v[j]     += bl0[j];
            v[4 + j] += bl1[j];
        }
        float s = 0.f, s2 = 0.f;
#pragma unroll
        for (int j = 0; j < 8; j++) { s += v[j]; s2 += v[j] * v[j]; }
#pragma unroll
        for (int m = 8; m > 0; m >>= 1) {
            s  += __shfl_xor_sync(0xffffffffu, s,  m);
            s2 += __shfl_xor_sync(0xffffffffu, s2, m);
        }
        float mu  = s * (1.f / 128.f);
        float var = s2 * (1.f / 128.f) - mu * mu;
        float rs  = rsqrtf(var + LN_EPS);
        if (row < N_NODES) {
            float4 xo0 = *reinterpret_cast<const float4*>(&xin[(size_t)row * HID + c0]);
            float4 xo1 = *reinterpret_cast<const float4*>(&xin[(size_t)row * HID + c1]);
            float4 o0, o1;
            o0.x = xo0.x + 0.5f * fmaxf((v[0] - mu) * rs * gm0[0] + be0[0], 0.f);
            o0.y = xo0.y + 0.5f * fmaxf((v[1] - mu) * rs * gm0[1] + be0[1], 0.f);
            o0.z = xo0.z + 0.5f * fmaxf((v[2] - mu) * rs * gm0[2] + be0[2], 0.f);
            o0.w = xo0.w + 0.5f * fmaxf((v[3] - mu) * rs * gm0[3] + be0[3], 0.f);
            o1.x = xo1.x + 0.5f * fmaxf((v[4] - mu) * rs * gm1[0] + be1[0], 0.f);
            o1.y = xo1.y + 0.5f * fmaxf((v[5] - mu) * rs * gm1[1] + be1[1], 0.f);
            o1.z = xo1.z + 0.5f * fmaxf((v[6] - mu) * rs * gm1[2] + be1[2], 0.f);
            o1.w = xo1.w + 0.5f * fmaxf((v[7] - mu) * rs * gm1[3] + be1[3], 0.f);
            *reinterpret_cast<float4*>(&xout[(size_t)row * HID + c0]) = o0;
            *reinterpret_cast<float4*>(&xout[(size_t)row * HID + c1]) = o1;
        }
    }
}

// ------------------------------------------------------------------
// head: out = relu(x @ wh1 + bh1) @ wh2 + bh2   (fused; shfl for 64->1)
// B pre-paired: Bs2[k][c] = (wh1[k][c], wh1[k][c+32]); 1x LDS.128 per k.
// ------------------------------------------------------------------
__global__ __launch_bounds__(256) void head_kernel(
    const float* __restrict__ xin,
    const float* __restrict__ wh1, const float* __restrict__ bh1,
    const float* __restrict__ wh2, const float* __restrict__ bh2,
    float* __restrict__ out)
{
    __shared__ float As[64 * 32];   // 8 KB
    __shared__ u64   Bs2[32 * 32];  // 8 KB
    int tid = threadIdx.x;
    int tx = tid & 15, ty = tid >> 4;
    int row0 = blockIdx.x * 64;

    u64 acc2[4][2];
#pragma unroll
    for (int i = 0; i < 4; i++) { acc2[i][0] = 0ull; acc2[i][1] = 0ull; }

    for (int kt = 0; kt < 4; kt++) {
        int kg0 = kt * 32;
#pragma unroll
        for (int p = 0; p < 8; p++) {
            int idx = tid + p * 256;
            int r = idx >> 5, k = idx & 31;
            int row = row0 + r;
            As[r * 32 + k] = (row < N_NODES) ? xin[(size_t)row * HID + kg0 + k] : 0.f;
        }
#pragma unroll
        for (int p = 0; p < 4; p++) {
            int idx = tid + p * 256;    // 0..1023
            int k = idx >> 5, c = idx & 31;
            const float* wsrc = wh1 + (kg0 + k) * 64;
            float lo = wsrc[c];
            float hi = wsrc[c + 32];
            u64 pr; PACK2(pr, lo, hi);
            Bs2[k * 32 + c] = pr;
        }
        __syncthreads();
#pragma unroll
        for (int k = 0; k < 32; k++) {
            u64 a2[4];
#pragma unroll
            for (int i = 0; i < 4; i++) {
                float a = As[(ty * 4 + i) * 32 + k];
                PACK_DUP(a2[i], a);
            }
            // pairs: (2tx, 32+2tx), (2tx+1, 32+2tx+1)
            ulonglong2 q = *reinterpret_cast<const ulonglong2*>(&Bs2[k * 32 + tx * 2]);
            u64 b2[2] = {q.x, q.y};
#pragma unroll
            for (int i = 0; i < 4; i++) {
                FMA2(acc2[i][0], a2[i], b2[0]);
                FMA2(acc2[i][1], a2[i], b2[1]);
            }
        }
        __syncthreads();
    }

    // cols owned: {2tx, 2tx+1, 32+2tx, 32+2tx+1}
    float b1v[4], w2v[4];
#pragma unroll
    for (int j = 0; j < 2; j++) {
        b1v[j]     = bh1[tx * 2 + j];      w2v[j]     = wh2[tx * 2 + j];
        b1v[2 + j] = bh1[32 + tx * 2 + j]; w2v[2 + j] = wh2[32 + tx * 2 + j];
    }
    float bo = bh2[0];
#pragma unroll
    for (int i = 0; i < 4; i++) {
        float vv[4];
        UNPACK2(vv[0], vv[2], acc2[i][0]);
        UNPACK2(vv[1], vv[3], acc2[i][1]);
        float p = 0.f;
#pragma unroll
        for (int j = 0; j < 4; j++)
            p += fmaxf(vv[j] + b1v[j], 0.f) * w2v[j];
#pragma unroll
        for (int m = 8; m > 0; m >>= 1)
            p += __shfl_xor_sync(0xffffffffu, p, m);
        int row = row0 + ty * 4 + i;
        if (tx == 0 && row < N_NODES) out[row] = p + bo;
    }
}

// ------------------------------------------------------------------
extern "C" void kernel_launch(void* const* d_in, const int* in_sizes, int n_in,
                              void* d_out, int out_size)
{
    const float* x_num = (const float*)d_in[0];
    const int*   x_cat = (const int*)d_in[1];
    const int*   edge  = (const int*)d_in[2];
    const float* emb0  = (const float*)d_in[3];
    const float* emb1  = (const float*)d_in[4];
    const float* emb2  = (const float*)d_in[5];
    const float* emb3  = (const float*)d_in[6];
    const float* w_in  = (const float*)d_in[7];
    const float* b_in  = (const float*)d_in[8];
    const float* w1l   = (const float*)d_in[9];
    const float* b1l   = (const float*)d_in[10];
    const float* w1r   = (const float*)d_in[11];
    const float* w2l   = (const float*)d_in[12];
    const float* b2l   = (const float*)d_in[13];
    const float* w2r   = (const float*)d_in[14];
    const float* g1    = (const float*)d_in[15];
    const float* be1   = (const float*)d_in[16];
    const float* g2    = (const float*)d_in[17];
    const float* be2   = (const float*)d_in[18];
    const float* wh1   = (const float*)d_in[19];
    const float* bh1   = (const float*)d_in[20];
    const float* wh2   = (const float*)d_in[21];
    const float* bh2   = (const float*)d_in[22];
    float* out = (float*)d_out;

    int E = in_sizes[2] / 2;
    const int* src = edge;
    const int* dst = edge + E;

    int node_blocks32 = (N_NODES + 31) / 32;
    int node_blocks64 = (N_NODES + 63) / 64;
    int eblocks = (E + 255) / 256;

    // device-global ping-pong buffers
    float *xA, *xB;
    cudaGetSymbolAddress((void**)&xA, g_xA);
    cudaGetSymbolAddress((void**)&xB, g_xB);

    // CSR build (edge structure only)
    zero_deg_kernel<<<NB_SCAN, 256>>>();
    hist_kernel<<<eblocks, 256>>>(dst, E);
    scan1_kernel<<<NB_SCAN, 256>>>();
    scan2_kernel<<<1, 512>>>();
    scan3_kernel<<<NB_SCAN, 256>>>(E);
    fill_kernel<<<eblocks, 256>>>(src, dst, E);

    // input MLP -> xA
    input_kernel<<<node_blocks32, 128>>>(x_num, x_cat, emb0, emb1, emb2, emb3, w_in, b_in, xA);

    // layer 1: xA -> xB ; layer 2: xB -> xA  (gather fused, ping-pong)
    sage_kernel<<<node_blocks64, 256>>>(xA, xB, w1l, b1l, w1r, g1, be1);
    sage_kernel<<<node_blocks64, 256>>>(xB, xA, w2l, b2l, w2r, g2, be2);

    head_kernel<<<node_blocks64, 256>>>(xA, wh1, bh1, wh2, bh2, out);
}

// round 10
// speedup vs baseline: 1.0898x; 1.0898x over previous
#include <cuda_runtime.h>

#define N_NODES 100000
#define E_MAX   1600000
#define HID 128
#define NUM_IN 32
#define IN_DIM 71
#define LN_EPS 1e-5f
#define NB_SCAN ((N_NODES + 255) / 256)   // 391

// ---- packed fp32x2 helpers (sm_103a FFMA2: full fp32 precision, 2x rate) ----
#define FMA2(acc, a, b) \
    asm("fma.rn.f32x2 %0, %1, %2, %0;" : "+l"(acc) : "l"(a), "l"(b))
#define PACK_DUP(dst, x) do { \
    unsigned int _u = __float_as_uint(x); \
    asm("mov.b64 %0, {%1,%1};" : "=l"(dst) : "r"(_u)); } while (0)
#define PACK2(dst, lo, hi) \
    asm("mov.b64 %0, {%1,%2};" : "=l"(dst) : "r"(__float_as_uint(lo)), "r"(__float_as_uint(hi)))
#define UNPACK2(lo, hi, v) do { \
    unsigned int _l, _h; \
    asm("mov.b64 {%0,%1}, %2;" : "=r"(_l), "=r"(_h) : "l"(v)); \
    lo = __uint_as_float(_l); hi = __uint_as_float(_h); } while (0)

typedef unsigned long long u64;

// ---- scratch (device globals; no allocation allowed) ----
__device__ __align__(16) float g_xA[N_NODES * HID];   // ping
__device__ __align__(16) float g_xB[N_NODES * HID];   // pong
__device__ int g_deg[N_NODES];
__device__ int g_rowptr[N_NODES + 1];
__device__ int g_cursor[N_NODES];
__device__ int g_csr[E_MAX];                          // src ids grouped by dst
__device__ int g_bsum[512];
__device__ int g_boff[512];

// ------------------------------------------------------------------
// CSR build: zero deg -> histogram -> 2-level exclusive scan -> fill
// ------------------------------------------------------------------
__global__ void zero_deg_kernel() {
    int i = blockIdx.x * blockDim.x + threadIdx.x;
    if (i < N_NODES) g_deg[i] = 0;
}

__global__ void hist_kernel(const int* __restrict__ dst, int E) {
    int i = blockIdx.x * blockDim.x + threadIdx.x;
    if (i < E) atomicAdd(&g_deg[dst[i]], 1);
}

__global__ __launch_bounds__(256) void scan1_kernel() {
    int tid = threadIdx.x;
    int lane = tid & 31, wid = tid >> 5;
    int i = blockIdx.x * 256 + tid;
    int v = (i < N_NODES) ? g_deg[i] : 0;
    int x = v;
#pragma unroll
    for (int o = 1; o < 32; o <<= 1) {
        int y = __shfl_up_sync(0xffffffffu, x, o);
        if (lane >= o) x += y;
    }
    __shared__ int wsum[8];
    if (lane == 31) wsum[wid] = x;
    __syncthreads();
    if (tid == 0) {
        int run = 0;
#pragma unroll
        for (int w = 0; w < 8; w++) { int t = wsum[w]; wsum[w] = run; run += t; }
        g_bsum[blockIdx.x] = run;
    }
    __syncthreads();
    int excl = x - v + wsum[wid];
    if (i < N_NODES) g_rowptr[i] = excl;
}

__global__ __launch_bounds__(512) void scan2_kernel() {
    __shared__ int s[512];
    int tid = threadIdx.x;
    int v = (tid < NB_SCAN) ? g_bsum[tid] : 0;
    s[tid] = v;
    __syncthreads();
    for (int o = 1; o < 512; o <<= 1) {
        int t = (tid >= o) ? s[tid - o] : 0;
        __syncthreads();
        s[tid] += t;
        __syncthreads();
    }
    if (tid < NB_SCAN) g_boff[tid] = s[tid] - v;   // exclusive
}

__global__ void scan3_kernel(int E) {
    int i = blockIdx.x * blockDim.x + threadIdx.x;
    if (i < N_NODES) {
        int v = g_rowptr[i] + g_boff[blockIdx.x];
        g_rowptr[i] = v;
        g_cursor[i] = v;
    }
    if (i == 0) g_rowptr[N_NODES] = E;
}

__global__ void fill_kernel(const int* __restrict__ src, const int* __restrict__ dst, int E) {
    int i = blockIdx.x * blockDim.x + threadIdx.x;
    if (i < E) {
        int d = dst[i];
        int pos = atomicAdd(&g_cursor[d], 1);
        g_csr[pos] = src[i];
    }
}

// ------------------------------------------------------------------
// input: x = relu(concat(x_num, emb lookups) @ w_in + b_in)
// ------------------------------------------------------------------
__global__ __launch_bounds__(128) void input_kernel(
    const float* __restrict__ x_num, const int* __restrict__ x_cat,
    const float* __restrict__ emb0, const float* __restrict__ emb1,
    const float* __restrict__ emb2, const float* __restrict__ emb3,
    const float* __restrict__ w_in, const float* __restrict__ b_in,
    float* __restrict__ xout)
{
    __shared__ float ws[IN_DIM * HID];       // 36352 B
    __shared__ float insT[IN_DIM * 32];      // k-major: insT[k*32 + n], 9088 B
    int tid = threadIdx.x;
    for (int i = tid; i < IN_DIM * HID; i += 128) ws[i] = w_in[i];

    int node0 = blockIdx.x * 32;
    for (int i = tid; i < 32 * NUM_IN; i += 128) {
        int n = i / NUM_IN, k = i % NUM_IN;
        int node = node0 + n;
        insT[k * 32 + n] = (node < N_NODES) ? x_num[node * NUM_IN + k] : 0.f;
    }
    for (int i = tid; i < 32 * 39; i += 128) {
        int n = i / 39, j = i % 39;
        int node = node0 + n;
        float v = 0.f;
        if (node < N_NODES) {
            if (j < 10)      v = emb0[x_cat[node * 4 + 0] * 10 + j];
            else if (j < 16) v = emb1[x_cat[node * 4 + 1] * 6 + (j - 10)];
            else if (j < 21) v = emb2[x_cat[node * 4 + 2] * 5 + (j - 16)];
            else             v = emb3[x_cat[node * 4 + 3] * 18 + (j - 21)];
        }
        insT[(NUM_IN + j) * 32 + n] = v;
    }
    __syncthreads();

    u64 acc2[16];
#pragma unroll
    for (int p = 0; p < 16; p++) acc2[p] = 0ull;

    for (int k = 0; k < IN_DIM; k++) {
        float w = ws[k * HID + tid];
        u64 w2; PACK_DUP(w2, w);
        const u64* ip = reinterpret_cast<const u64*>(&insT[k * 32]);
#pragma unroll
        for (int p = 0; p < 16; p++) {
            u64 in2 = ip[p];
            FMA2(acc2[p], w2, in2);
        }
    }
    float b = b_in[tid];
#pragma unroll
    for (int p = 0; p < 16; p++) {
        float lo, hi;
        UNPACK2(lo, hi, acc2[p]);
        int n0 = node0 + 2 * p;
        if (n0 < N_NODES)     xout[(size_t)n0 * HID + tid]       = fmaxf(lo + b, 0.f);
        if (n0 + 1 < N_NODES) xout[(size_t)(n0 + 1) * HID + tid] = fmaxf(hi + b, 0.f);
    }
}

// ------------------------------------------------------------------
// SAGE update (gather + GEMM + LN fused), ping-pong safe.
// BM=64, BN=128, BK=32, 256 threads (16x16).
// Thread (tx,ty): rows ty*4..+3, cols {4tx..4tx+3} (lo) and {64+4tx..+3} (hi).
// B loads: 2x LDS.128 per k, conflict-free; A loads: LDS.64 per row per 2 k.
// ------------------------------------------------------------------
__global__ __launch_bounds__(256) void sage_kernel(
    const float* __restrict__ xin, float* __restrict__ xout,
    const float* __restrict__ wl, const float* __restrict__ bl,
    const float* __restrict__ wr,
    const float* __restrict__ gam, const float* __restrict__ bet)
{
    __shared__ float sMean[64 * 128];  // 32 KB
    __shared__ float As[64 * 32];      // 8 KB (xin tile for kt>=4)
    __shared__ float Bs[32 * 128];     // 16 KB

    int tid = threadIdx.x;
    int row0 = blockIdx.x * 64;
    int warp = tid >> 5, lane = tid & 31;
    const float4* x4 = reinterpret_cast<const float4*>(xin);

    // ---- phase 1: gather mean (warp per row, 8 rows per warp) ----
#pragma unroll 1
    for (int j = 0; j < 8; j++) {
        int r = warp * 8 + j;
        int row = row0 + r;
        int beg = 0, end = 0;
        if (row < N_NODES) { beg = g_rowptr[row]; end = g_rowptr[row + 1]; }
        float4 a0 = make_float4(0.f, 0.f, 0.f, 0.f);
        float4 a1 = a0, a2 = a0, a3 = a0;
        int e = beg;
        for (; e + 4 <= end; e += 4) {
            int s0 = __ldg(&g_csr[e]);
            int s1 = __ldg(&g_csr[e + 1]);
            int s2 = __ldg(&g_csr[e + 2]);
            int s3 = __ldg(&g_csr[e + 3]);
            float4 v0 = x4[(size_t)s0 * 32 + lane];
            float4 v1 = x4[(size_t)s1 * 32 + lane];
            float4 v2 = x4[(size_t)s2 * 32 + lane];
            float4 v3 = x4[(size_t)s3 * 32 + lane];
            a0.x += v0.x; a0.y += v0.y; a0.z += v0.z; a0.w += v0.w;
            a1.x += v1.x; a1.y += v1.y; a1.z += v1.z; a1.w += v1.w;
            a2.x += v2.x; a2.y += v2.y; a2.z += v2.z; a2.w += v2.w;
            a3.x += v3.x; a3.y += v3.y; a3.z += v3.z; a3.w += v3.w;
        }
        for (; e < end; e++) {
            int s = __ldg(&g_csr[e]);
            float4 v = x4[(size_t)s * 32 + lane];
            a0.x += v.x; a0.y += v.y; a0.z += v.z; a0.w += v.w;
        }
        float inv = 1.f / fmaxf((float)(end - beg), 1.f);
        float4 m;
        m.x = (a0.x + a1.x + a2.x + a3.x) * inv;
        m.y = (a0.y + a1.y + a2.y + a3.y) * inv;
        m.z = (a0.z + a1.z + a2.z + a3.z) * inv;
        m.w = (a0.w + a1.w + a2.w + a3.w) * inv;
        reinterpret_cast<float4*>(sMean)[r * 32 + lane] = m;
    }
    __syncthreads();

    // ---- phase 2: GEMM ----
    int tx = tid & 15, ty = tid >> 4;
    u64 acc2[4][4];   // [row i][j]: lo = col 4tx+j, hi = col 64+4tx+j
#pragma unroll
    for (int i = 0; i < 4; i++)
#pragma unroll
        for (int j = 0; j < 4; j++) acc2[i][j] = 0ull;

#pragma unroll 1
    for (int kt = 0; kt < 8; kt++) {
        int kg0 = kt * 32;
        // stage xin tile for kg>=128 (mean tile already resident in sMean)
        if (kt >= 4) {
#pragma unroll
            for (int p = 0; p < 8; p++) {
                int idx = tid + p * 256;
                int r = idx >> 5, k = idx & 31;
                int row = row0 + r;
                As[r * 32 + k] = (row < N_NODES)
                    ? xin[(size_t)row * HID + (kg0 - 128 + k)] : 0.f;
            }
        }
        // stage B tile: B[k][c] = (kg<128) ? wl : wr
#pragma unroll
        for (int p = 0; p < 16; p++) {
            int idx = tid + p * 256;
            int k = idx >> 7, c = idx & 127;
            int kg = kg0 + k;
            Bs[k * 128 + c] = (kg < 128) ? wl[kg * 128 + c]
                                         : wr[(kg - 128) * 128 + c];
        }
        __syncthreads();

        const float* Abase = (kt < 4) ? (sMean + kg0) : As;
        int astr = (kt < 4) ? 128 : 32;
#pragma unroll
        for (int kp = 0; kp < 16; kp++) {
            int k0 = kp * 2;
            float2 af[4];
#pragma unroll
            for (int i = 0; i < 4; i++)
                af[i] = *reinterpret_cast<const float2*>(&Abase[(ty * 4 + i) * astr + k0]);
            // ---- k = k0 ----
            {
                float4 blv = *reinterpret_cast<const float4*>(&Bs[k0 * 128 + tx * 4]);
                float4 bhv = *reinterpret_cast<const float4*>(&Bs[k0 * 128 + 64 + tx * 4]);
                u64 b2[4];
                PACK2(b2[0], blv.x, bhv.x);
                PACK2(b2[1], blv.y, bhv.y);
                PACK2(b2[2], blv.z, bhv.z);
                PACK2(b2[3], blv.w, bhv.w);
                u64 a2[4];
#pragma unroll
                for (int i = 0; i < 4; i++) PACK_DUP(a2[i], af[i].x);
#pragma unroll
                for (int i = 0; i < 4; i++)
#pragma unroll
                    for (int j = 0; j < 4; j++)
                        FMA2(acc2[i][j], a2[i], b2[j]);
            }
            // ---- k = k0 + 1 ----
            {
                float4 blv = *reinterpret_cast<const float4*>(&Bs[(k0 + 1) * 128 + tx * 4]);
                float4 bhv = *reinterpret_cast<const float4*>(&Bs[(k0 + 1) * 128 + 64 + tx * 4]);
                u64 b2[4];
                PACK2(b2[0], blv.x, bhv.x);
                PACK2(b2[1], blv.y, bhv.y);
                PACK2(b2[2], blv.z, bhv.z);
                PACK2(b2[3], blv.w, bhv.w);
                u64 a2[4];
#pragma unroll
                for (int i = 0; i < 4; i++) PACK_DUP(a2[i], af[i].y);
#pragma unroll
                for (int i = 0; i < 4; i++)
#pragma unroll
                    for (int j = 0; j < 4; j++)
                        FMA2(acc2[i][j], a2[i], b2[j]);
            }
        }
        __syncthreads();
    }

    // epilogue: +bias, LayerNorm (16-lane shfl reduce), relu, residual
    int c0 = tx * 4;          // lo cols c0..c0+3
    int c1 = 64 + tx * 4;     // hi cols c1..c1+3
    float bl0[4], gm0[4], be0[4], bl1[4], gm1[4], be1[4];
#pragma unroll
    for (int j = 0; j < 4; j++) {
        bl0[j] = bl[c0 + j];  gm0[j] = gam[c0 + j];  be0[j] = bet[c0 + j];
        bl1[j] = bl[c1 + j];  gm1[j] = gam[c1 + j];  be1[j] = bet[c1 + j];
    }
#pragma unroll
    for (int i = 0; i < 4; i++) {
        int row = row0 + ty * 4 + i;
        float v[8];   // v[0..3] lo cols, v[4..7] hi cols
#pragma unroll
        for (int j = 0; j < 4; j++) {
            UNPACK2(v[j], v[4 + j], acc2[i][j]);
            v[j]     += bl0[j];
            v[4 + j] += bl1[j];
        }
        float s = 0.f, s2 = 0.f;
#pragma unroll
        for (int j = 0; j < 8; j++) { s += v[j]; s2 += v[j] * v[j]; }
#pragma unroll
        for (int m = 8; m > 0; m >>= 1) {
            s  += __shfl_xor_sync(0xffffffffu, s,  m);
            s2 += __shfl_xor_sync(0xffffffffu, s2, m);
        }
        float mu  = s * (1.f / 128.f);
        float var = s2 * (1.f / 128.f) - mu * mu;
        float rs  = rsqrtf(var + LN_EPS);
        if (row < N_NODES) {
            float4 xo0 = *reinterpret_cast<const float4*>(&xin[(size_t)row * HID + c0]);
            float4 xo1 = *reinterpret_cast<const float4*>(&xin[(size_t)row * HID + c1]);
            float4 o0, o1;
            o0.x = xo0.x + 0.5f * fmaxf((v[0] - mu) * rs * gm0[0] + be0[0], 0.f);
            o0.y = xo0.y + 0.5f * fmaxf((v[1] - mu) * rs * gm0[1] + be0[1], 0.f);
            o0.z = xo0.z + 0.5f * fmaxf((v[2] - mu) * rs * gm0[2] + be0[2], 0.f);
            o0.w = xo0.w + 0.5f * fmaxf((v[3] - mu) * rs * gm0[3] + be0[3], 0.f);
            o1.x = xo1.x + 0.5f * fmaxf((v[4] - mu) * rs * gm1[0] + be1[0], 0.f);
            o1.y = xo1.y + 0.5f * fmaxf((v[5] - mu) * rs * gm1[1] + be1[1], 0.f);
            o1.z = xo1.z + 0.5f * fmaxf((v[6] - mu) * rs * gm1[2] + be1[2], 0.f);
            o1.w = xo1.w + 0.5f * fmaxf((v[7] - mu) * rs * gm1[3] + be1[3], 0.f);
            *reinterpret_cast<float4*>(&xout[(size_t)row * HID + c0]) = o0;
            *reinterpret_cast<float4*>(&xout[(size_t)row * HID + c1]) = o1;
        }
    }
}

// ------------------------------------------------------------------
// head: out = relu(x @ wh1 + bh1) @ wh2 + bh2   (fused; shfl for 64->1)
// ------------------------------------------------------------------
__global__ __launch_bounds__(256) void head_kernel(
    const float* __restrict__ xin,
    const float* __restrict__ wh1, const float* __restrict__ bh1,
    const float* __restrict__ wh2, const float* __restrict__ bh2,
    float* __restrict__ out)
{
    __shared__ float As[64 * 32];   // 8 KB
    __shared__ float Bs[32 * 64];   // 8 KB
    int tid = threadIdx.x;
    int tx = tid & 15, ty = tid >> 4;
    int row0 = blockIdx.x * 64;

    u64 acc2[4][2];
#pragma unroll
    for (int i = 0; i < 4; i++) { acc2[i][0] = 0ull; acc2[i][1] = 0ull; }

    for (int kt = 0; kt < 4; kt++) {
        int kg0 = kt * 32;
#pragma unroll
        for (int p = 0; p < 8; p++) {
            int idx = tid + p * 256;
            int r = idx >> 5, k = idx & 31;
            int row = row0 + r;
            As[r * 32 + k] = (row < N_NODES) ? xin[(size_t)row * HID + kg0 + k] : 0.f;
        }
#pragma unroll
        for (int p = 0; p < 8; p++) {
            int idx = tid + p * 256;
            int k = idx >> 6, c = idx & 63;
            Bs[k * 64 + c] = wh1[(kg0 + k) * 64 + c];
        }
        __syncthreads();
#pragma unroll
        for (int kp = 0; kp < 16; kp++) {
            int k0 = kp * 2;
            float2 af[4];
#pragma unroll
            for (int i = 0; i < 4; i++)
                af[i] = *reinterpret_cast<const float2*>(&As[(ty * 4 + i) * 32 + k0]);
#pragma unroll
            for (int kk = 0; kk < 2; kk++) {
                int k = k0 + kk;
                float2 blv = *reinterpret_cast<const float2*>(&Bs[k * 64 + tx * 2]);
                float2 bhv = *reinterpret_cast<const float2*>(&Bs[k * 64 + 32 + tx * 2]);
                u64 b2[2];
                PACK2(b2[0], blv.x, bhv.x);
                PACK2(b2[1], blv.y, bhv.y);
                u64 a2[4];
#pragma unroll
                for (int i = 0; i < 4; i++)
                    PACK_DUP(a2[i], (kk == 0) ? af[i].x : af[i].y);
#pragma unroll
                for (int i = 0; i < 4; i++) {
                    FMA2(acc2[i][0], a2[i], b2[0]);
                    FMA2(acc2[i][1], a2[i], b2[1]);
                }
            }
        }
        __syncthreads();
    }

    // cols owned: {2tx, 2tx+1, 32+2tx, 32+2tx+1}
    float b1v[4], w2v[4];
#pragma unroll
    for (int j = 0; j < 2; j++) {
        b1v[j]     = bh1[tx * 2 + j];      w2v[j]     = wh2[tx * 2 + j];
        b1v[2 + j] = bh1[32 + tx * 2 + j]; w2v[2 + j] = wh2[32 + tx * 2 + j];
    }
    float bo = bh2[0];
#pragma unroll
    for (int i = 0; i < 4; i++) {
        float vv[4];
        UNPACK2(vv[0], vv[2], acc2[i][0]);
        UNPACK2(vv[1], vv[3], acc2[i][1]);
        float p = 0.f;
#pragma unroll
        for (int j = 0; j < 4; j++)
            p += fmaxf(vv[j] + b1v[j], 0.f) * w2v[j];
#pragma unroll
        for (int m = 8; m > 0; m >>= 1)
            p += __shfl_xor_sync(0xffffffffu, p, m);
        int row = row0 + ty * 4 + i;
        if (tx == 0 && row < N_NODES) out[row] = p + bo;
    }
}

// ------------------------------------------------------------------
extern "C" void kernel_launch(void* const* d_in, const int* in_sizes, int n_in,
                              void* d_out, int out_size)
{
    const float* x_num = (const float*)d_in[0];
    const int*   x_cat = (const int*)d_in[1];
    const int*   edge  = (const int*)d_in[2];
    const float* emb0  = (const float*)d_in[3];
    const float* emb1  = (const float*)d_in[4];
    const float* emb2  = (const float*)d_in[5];
    const float* emb3  = (const float*)d_in[6];
    const float* w_in  = (const float*)d_in[7];
    const float* b_in  = (const float*)d_in[8];
    const float* w1l   = (const float*)d_in[9];
    const float* b1l   = (const float*)d_in[10];
    const float* w1r   = (const float*)d_in[11];
    const float* w2l   = (const float*)d_in[12];
    const float* b2l   = (const float*)d_in[13];
    const float* w2r   = (const float*)d_in[14];
    const float* g1    = (const float*)d_in[15];
    const float* be1   = (const float*)d_in[16];
    const float* g2    = (const float*)d_in[17];
    const float* be2   = (const float*)d_in[18];
    const float* wh1   = (const float*)d_in[19];
    const float* bh1   = (const float*)d_in[20];
    const float* wh2   = (const float*)d_in[21];
    const float* bh2   = (const float*)d_in[22];
    float* out = (float*)d_out;

    int E = in_sizes[2] / 2;
    const int* src = edge;
    const int* dst = edge + E;

    int node_blocks32 = (N_NODES + 31) / 32;
    int node_blocks64 = (N_NODES + 63) / 64;
    int eblocks = (E + 255) / 256;

    // device-global ping-pong buffers
    float *xA, *xB;
    cudaGetSymbolAddress((void**)&xA, g_xA);
    cudaGetSymbolAddress((void**)&xB, g_xB);

    // CSR build (edge structure only)
    zero_deg_kernel<<<NB_SCAN, 256>>>();
    hist_kernel<<<eblocks, 256>>>(dst, E);
    scan1_kernel<<<NB_SCAN, 256>>>();
    scan2_kernel<<<1, 512>>>();
    scan3_kernel<<<NB_SCAN, 256>>>(E);
    fill_kernel<<<eblocks, 256>>>(src, dst, E);

    // input MLP -> xA
    input_kernel<<<node_blocks32, 128>>>(x_num, x_cat, emb0, emb1, emb2, emb3, w_in, b_in, xA);

    // layer 1: xA -> xB ; layer 2: xB -> xA  (gather fused, ping-pong)
    sage_kernel<<<node_blocks64, 256>>>(xA, xB, w1l, b1l, w1r, g1, be1);
    sage_kernel<<<node_blocks64, 256>>>(xB, xA, w2l, b2l, w2r, g2, be2);

    head_kernel<<<node_blocks64, 256>>>(xA, wh1, bh1, wh2, bh2, out);
}

// round 11
// speedup vs baseline: 1.1142x; 1.0224x over previous
#include <cuda_runtime.h>

#define N_NODES 100000
#define E_MAX   1600000
#define HID 128
#define NUM_IN 32
#define IN_DIM 71
#define LN_EPS 1e-5f
#define NB_SCAN ((N_NODES + 255) / 256)   // 391

// ---- packed fp32x2 helpers (sm_103a FFMA2: full fp32 precision, 2x rate) ----
#define FMA2(acc, a, b) \
    asm("fma.rn.f32x2 %0, %1, %2, %0;" : "+l"(acc) : "l"(a), "l"(b))
#define PACK_DUP(dst, x) do { \
    unsigned int _u = __float_as_uint(x); \
    asm("mov.b64 %0, {%1,%1};" : "=l"(dst) : "r"(_u)); } while (0)
#define PACK2(dst, lo, hi) \
    asm("mov.b64 %0, {%1,%2};" : "=l"(dst) : "r"(__float_as_uint(lo)), "r"(__float_as_uint(hi)))
#define UNPACK2(lo, hi, v) do { \
    unsigned int _l, _h; \
    asm("mov.b64 {%0,%1}, %2;" : "=r"(_l), "=r"(_h) : "l"(v)); \
    lo = __uint_as_float(_l); hi = __uint_as_float(_h); } while (0)

typedef unsigned long long u64;

// ---- scratch (device globals; no allocation allowed) ----
__device__ __align__(16) float g_xA[N_NODES * HID];   // ping
__device__ __align__(16) float g_xB[N_NODES * HID];   // pong
__device__ int g_deg[N_NODES];
__device__ int g_rowptr[N_NODES + 1];
__device__ int g_cursor[N_NODES];
__device__ int g_csr[E_MAX];                          // src ids grouped by dst
__device__ int g_bsum[512];
__device__ int g_boff[512];

// ------------------------------------------------------------------
// CSR build: zero deg -> histogram -> 2-level exclusive scan -> fill
// ------------------------------------------------------------------
__global__ void zero_deg_kernel() {
    int i = blockIdx.x * blockDim.x + threadIdx.x;
    if (i < N_NODES) g_deg[i] = 0;
}

__global__ void hist_kernel(const int* __restrict__ dst, int E) {
    int i = blockIdx.x * blockDim.x + threadIdx.x;
    if (i < E) atomicAdd(&g_deg[dst[i]], 1);
}

__global__ __launch_bounds__(256) void scan1_kernel() {
    int tid = threadIdx.x;
    int lane = tid & 31, wid = tid >> 5;
    int i = blockIdx.x * 256 + tid;
    int v = (i < N_NODES) ? g_deg[i] : 0;
    int x = v;
#pragma unroll
    for (int o = 1; o < 32; o <<= 1) {
        int y = __shfl_up_sync(0xffffffffu, x, o);
        if (lane >= o) x += y;
    }
    __shared__ int wsum[8];
    if (lane == 31) wsum[wid] = x;
    __syncthreads();
    if (tid == 0) {
        int run = 0;
#pragma unroll
        for (int w = 0; w < 8; w++) { int t = wsum[w]; wsum[w] = run; run += t; }
        g_bsum[blockIdx.x] = run;
    }
    __syncthreads();
    int excl = x - v + wsum[wid];
    if (i < N_NODES) g_rowptr[i] = excl;
}

__global__ __launch_bounds__(512) void scan2_kernel() {
    __shared__ int s[512];
    int tid = threadIdx.x;
    int v = (tid < NB_SCAN) ? g_bsum[tid] : 0;
    s[tid] = v;
    __syncthreads();
    for (int o = 1; o < 512; o <<= 1) {
        int t = (tid >= o) ? s[tid - o] : 0;
        __syncthreads();
        s[tid] += t;
        __syncthreads();
    }
    if (tid < NB_SCAN) g_boff[tid] = s[tid] - v;   // exclusive
}

__global__ void scan3_kernel(int E) {
    int i = blockIdx.x * blockDim.x + threadIdx.x;
    if (i < N_NODES) {
        int v = g_rowptr[i] + g_boff[blockIdx.x];
        g_rowptr[i] = v;
        g_cursor[i] = v;
    }
    if (i == 0) g_rowptr[N_NODES] = E;
}

__global__ void fill_kernel(const int* __restrict__ src, const int* __restrict__ dst, int E) {
    int i = blockIdx.x * blockDim.x + threadIdx.x;
    if (i < E) {
        int d = dst[i];
        int pos = atomicAdd(&g_cursor[d], 1);
        g_csr[pos] = src[i];
    }
}

// ------------------------------------------------------------------
// input: x = relu(concat(x_num, emb lookups) @ w_in + b_in)
// ------------------------------------------------------------------
__global__ __launch_bounds__(128) void input_kernel(
    const float* __restrict__ x_num, const int* __restrict__ x_cat,
    const float* __restrict__ emb0, const float* __restrict__ emb1,
    const float* __restrict__ emb2, const float* __restrict__ emb3,
    const float* __restrict__ w_in, const float* __restrict__ b_in,
    float* __restrict__ xout)
{
    __shared__ float ws[IN_DIM * HID];       // 36352 B
    __shared__ float insT[IN_DIM * 32];      // k-major: insT[k*32 + n], 9088 B
    int tid = threadIdx.x;
    for (int i = tid; i < IN_DIM * HID; i += 128) ws[i] = w_in[i];

    int node0 = blockIdx.x * 32;
    for (int i = tid; i < 32 * NUM_IN; i += 128) {
        int n = i / NUM_IN, k = i % NUM_IN;
        int node = node0 + n;
        insT[k * 32 + n] = (node < N_NODES) ? x_num[node * NUM_IN + k] : 0.f;
    }
    for (int i = tid; i < 32 * 39; i += 128) {
        int n = i / 39, j = i % 39;
        int node = node0 + n;
        float v = 0.f;
        if (node < N_NODES) {
            if (j < 10)      v = emb0[x_cat[node * 4 + 0] * 10 + j];
            else if (j < 16) v = emb1[x_cat[node * 4 + 1] * 6 + (j - 10)];
            else if (j < 21) v = emb2[x_cat[node * 4 + 2] * 5 + (j - 16)];
            else             v = emb3[x_cat[node * 4 + 3] * 18 + (j - 21)];
        }
        insT[(NUM_IN + j) * 32 + n] = v;
    }
    __syncthreads();

    u64 acc2[16];
#pragma unroll
    for (int p = 0; p < 16; p++) acc2[p] = 0ull;

    for (int k = 0; k < IN_DIM; k++) {
        float w = ws[k * HID + tid];
        u64 w2; PACK_DUP(w2, w);
        const u64* ip = reinterpret_cast<const u64*>(&insT[k * 32]);
#pragma unroll
        for (int p = 0; p < 16; p++) {
            u64 in2 = ip[p];
            FMA2(acc2[p], w2, in2);
        }
    }
    float b = b_in[tid];
#pragma unroll
    for (int p = 0; p < 16; p++) {
        float lo, hi;
        UNPACK2(lo, hi, acc2[p]);
        int n0 = node0 + 2 * p;
        if (n0 < N_NODES)     xout[(size_t)n0 * HID + tid]       = fmaxf(lo + b, 0.f);
        if (n0 + 1 < N_NODES) xout[(size_t)(n0 + 1) * HID + tid] = fmaxf(hi + b, 0.f);
    }
}

// ------------------------------------------------------------------
// SAGE update (gather + GEMM + LN fused), ping-pong safe.
// BM=64, BN=128, BK=32, 256 threads (16x16).
// Gather: 8 LDG.128 in flight per warp (latency hiding), warp per row.
// GEMM: conflict-free B loads (2x LDS.128/k) + float2 A loads per 2k.
// ------------------------------------------------------------------
__global__ __launch_bounds__(256) void sage_kernel(
    const float* __restrict__ xin, float* __restrict__ xout,
    const float* __restrict__ wl, const float* __restrict__ bl,
    const float* __restrict__ wr,
    const float* __restrict__ gam, const float* __restrict__ bet)
{
    __shared__ float sMean[64 * 128];  // 32 KB
    __shared__ float As[64 * 32];      // 8 KB (xin tile for kt>=4)
    __shared__ float Bs[32 * 128];     // 16 KB

    int tid = threadIdx.x;
    int row0 = blockIdx.x * 64;
    int warp = tid >> 5, lane = tid & 31;
    const float4* x4 = reinterpret_cast<const float4*>(xin);

    // ---- phase 1: gather mean (warp per row, 8 rows per warp) ----
#pragma unroll 1
    for (int j = 0; j < 8; j++) {
        int r = warp * 8 + j;
        int row = row0 + r;
        int beg = 0, end = 0;
        if (row < N_NODES) { beg = g_rowptr[row]; end = g_rowptr[row + 1]; }
        float4 a0 = make_float4(0.f, 0.f, 0.f, 0.f);
        float4 a1 = a0, a2 = a0, a3 = a0;
        int e = beg;
        // 8 independent loads in flight per iteration
#pragma unroll 1
        for (; e + 8 <= end; e += 8) {
            int s0 = __ldg(&g_csr[e]);
            int s1 = __ldg(&g_csr[e + 1]);
            int s2 = __ldg(&g_csr[e + 2]);
            int s3 = __ldg(&g_csr[e + 3]);
            int s4 = __ldg(&g_csr[e + 4]);
            int s5 = __ldg(&g_csr[e + 5]);
            int s6 = __ldg(&g_csr[e + 6]);
            int s7 = __ldg(&g_csr[e + 7]);
            float4 v0 = x4[(size_t)s0 * 32 + lane];
            float4 v1 = x4[(size_t)s1 * 32 + lane];
            float4 v2 = x4[(size_t)s2 * 32 + lane];
            float4 v3 = x4[(size_t)s3 * 32 + lane];
            float4 v4 = x4[(size_t)s4 * 32 + lane];
            float4 v5 = x4[(size_t)s5 * 32 + lane];
            float4 v6 = x4[(size_t)s6 * 32 + lane];
            float4 v7 = x4[(size_t)s7 * 32 + lane];
            a0.x += v0.x; a0.y += v0.y; a0.z += v0.z; a0.w += v0.w;
            a1.x += v1.x; a1.y += v1.y; a1.z += v1.z; a1.w += v1.w;
            a2.x += v2.x; a2.y += v2.y; a2.z += v2.z; a2.w += v2.w;
            a3.x += v3.x; a3.y += v3.y; a3.z += v3.z; a3.w += v3.w;
            a0.x += v4.x; a0.y += v4.y; a0.z += v4.z; a0.w += v4.w;
            a1.x += v5.x; a1.y += v5.y; a1.z += v5.z; a1.w += v5.w;
            a2.x += v6.x; a2.y += v6.y; a2.z += v6.z; a2.w += v6.w;
            a3.x += v7.x; a3.y += v7.y; a3.z += v7.z; a3.w += v7.w;
        }
        if (e + 4 <= end) {
            int s0 = __ldg(&g_csr[e]);
            int s1 = __ldg(&g_csr[e + 1]);
            int s2 = __ldg(&g_csr[e + 2]);
            int s3 = __ldg(&g_csr[e + 3]);
            float4 v0 = x4[(size_t)s0 * 32 + lane];
            float4 v1 = x4[(size_t)s1 * 32 + lane];
            float4 v2 = x4[(size_t)s2 * 32 + lane];
            float4 v3 = x4[(size_t)s3 * 32 + lane];
            a0.x += v0.x; a0.y += v0.y; a0.z += v0.z; a0.w += v0.w;
            a1.x += v1.x; a1.y += v1.y; a1.z += v1.z; a1.w += v1.w;
            a2.x += v2.x; a2.y += v2.y; a2.z += v2.z; a2.w += v2.w;
            a3.x += v3.x; a3.y += v3.y; a3.z += v3.z; a3.w += v3.w;
            e += 4;
        }
        for (; e < end; e++) {
            int s = __ldg(&g_csr[e]);
            float4 v = x4[(size_t)s * 32 + lane];
            a0.x += v.x; a0.y += v.y; a0.z += v.z; a0.w += v.w;
        }
        float inv = 1.f / fmaxf((float)(end - beg), 1.f);
        float4 m;
        m.x = (a0.x + a1.x + a2.x + a3.x) * inv;
        m.y = (a0.y + a1.y + a2.y + a3.y) * inv;
        m.z = (a0.z + a1.z + a2.z + a3.z) * inv;
        m.w = (a0.w + a1.w + a2.w + a3.w) * inv;
        reinterpret_cast<float4*>(sMean)[r * 32 + lane] = m;
    }
    __syncthreads();

    // ---- phase 2: GEMM ----
    int tx = tid & 15, ty = tid >> 4;
    u64 acc2[4][4];   // [row i][j]: lo = col 4tx+j, hi = col 64+4tx+j
#pragma unroll
    for (int i = 0; i < 4; i++)
#pragma unroll
        for (int j = 0; j < 4; j++) acc2[i][j] = 0ull;

#pragma unroll 1
    for (int kt = 0; kt < 8; kt++) {
        int kg0 = kt * 32;
        // stage xin tile for kg>=128 (mean tile already resident in sMean)
        if (kt >= 4) {
#pragma unroll
            for (int p = 0; p < 8; p++) {
                int idx = tid + p * 256;
                int r = idx >> 5, k = idx & 31;
                int row = row0 + r;
                As[r * 32 + k] = (row < N_NODES)
                    ? xin[(size_t)row * HID + (kg0 - 128 + k)] : 0.f;
            }
        }
        // stage B tile: B[k][c] = (kg<128) ? wl : wr
#pragma unroll
        for (int p = 0; p < 16; p++) {
            int idx = tid + p * 256;
            int k = idx >> 7, c = idx & 127;
            int kg = kg0 + k;
            Bs[k * 128 + c] = (kg < 128) ? wl[kg * 128 + c]
                                         : wr[(kg - 128) * 128 + c];
        }
        __syncthreads();

        const float* Abase = (kt < 4) ? (sMean + kg0) : As;
        int astr = (kt < 4) ? 128 : 32;
#pragma unroll
        for (int kp = 0; kp < 16; kp++) {
            int k0 = kp * 2;
            float2 af[4];
#pragma unroll
            for (int i = 0; i < 4; i++)
                af[i] = *reinterpret_cast<const float2*>(&Abase[(ty * 4 + i) * astr + k0]);
            // ---- k = k0 ----
            {
                float4 blv = *reinterpret_cast<const float4*>(&Bs[k0 * 128 + tx * 4]);
                float4 bhv = *reinterpret_cast<const float4*>(&Bs[k0 * 128 + 64 + tx * 4]);
                u64 b2[4];
                PACK2(b2[0], blv.x, bhv.x);
                PACK2(b2[1], blv.y, bhv.y);
                PACK2(b2[2], blv.z, bhv.z);
                PACK2(b2[3], blv.w, bhv.w);
                u64 a2[4];
#pragma unroll
                for (int i = 0; i < 4; i++) PACK_DUP(a2[i], af[i].x);
#pragma unroll
                for (int i = 0; i < 4; i++)
#pragma unroll
                    for (int j = 0; j < 4; j++)
                        FMA2(acc2[i][j], a2[i], b2[j]);
            }
            // ---- k = k0 + 1 ----
            {
                float4 blv = *reinterpret_cast<const float4*>(&Bs[(k0 + 1) * 128 + tx * 4]);
                float4 bhv = *reinterpret_cast<const float4*>(&Bs[(k0 + 1) * 128 + 64 + tx * 4]);
                u64 b2[4];
                PACK2(b2[0], blv.x, bhv.x);
                PACK2(b2[1], blv.y, bhv.y);
                PACK2(b2[2], blv.z, bhv.z);
                PACK2(b2[3], blv.w, bhv.w);
                u64 a2[4];
#pragma unroll
                for (int i = 0; i < 4; i++) PACK_DUP(a2[i], af[i].y);
#pragma unroll
                for (int i = 0; i < 4; i++)
#pragma unroll
                    for (int j = 0; j < 4; j++)
                        FMA2(acc2[i][j], a2[i], b2[j]);
            }
        }
        __syncthreads();
    }

    // epilogue: +bias, LayerNorm (16-lane shfl reduce), relu, residual
    int c0 = tx * 4;          // lo cols c0..c0+3
    int c1 = 64 + tx * 4;     // hi cols c1..c1+3
    float bl0[4], gm0[4], be0[4], bl1[4], gm1[4], be1[4];
#pragma unroll
    for (int j = 0; j < 4; j++) {
        bl0[j] = bl[c0 + j];  gm0[j] = gam[c0 + j];  be0[j] = bet[c0 + j];
        bl1[j] = bl[c1 + j];  gm1[j] = gam[c1 + j];  be1[j] = bet[c1 + j];
    }
#pragma unroll
    for (int i = 0; i < 4; i++) {
        int row = row0 + ty * 4 + i;
        float v[8];   // v[0..3] lo cols, v[4..7] hi cols
#pragma unroll
        for (int j = 0; j < 4; j++) {
            UNPACK2(v[j], v[4 + j], acc2[i][j]);
            v[j]     += bl0[j];
            v[4 + j] += bl1[j];
        }
        float s = 0.f, s2 = 0.f;
#pragma unroll
        for (int j = 0; j < 8; j++) { s += v[j]; s2 += v[j] * v[j]; }
#pragma unroll
        for (int m = 8; m > 0; m >>= 1) {
            s  += __shfl_xor_sync(0xffffffffu, s,  m);
            s2 += __shfl_xor_sync(0xffffffffu, s2, m);
        }
        float mu  = s * (1.f / 128.f);
        float var = s2 * (1.f / 128.f) - mu * mu;
        float rs  = rsqrtf(var + LN_EPS);
        if (row < N_NODES) {
            float4 xo0 = *reinterpret_cast<const float4*>(&xin[(size_t)row * HID + c0]);
            float4 xo1 = *reinterpret_cast<const float4*>(&xin[(size_t)row * HID + c1]);
            float4 o0, o1;
            o0.x = xo0.x + 0.5f * fmaxf((v[0] - mu) * rs * gm0[0] + be0[0], 0.f);
            o0.y = xo0.y + 0.5f * fmaxf((v[1] - mu) * rs * gm0[1] + be0[1], 0.f);
            o0.z = xo0.z + 0.5f * fmaxf((v[2] - mu) * rs * gm0[2] + be0[2], 0.f);
            o0.w = xo0.w + 0.5f * fmaxf((v[3] - mu) * rs * gm0[3] + be0[3], 0.f);
            o1.x = xo1.x + 0.5f * fmaxf((v[4] - mu) * rs * gm1[0] + be1[0], 0.f);
            o1.y = xo1.y + 0.5f * fmaxf((v[5] - mu) * rs * gm1[1] + be1[1], 0.f);
            o1.z = xo1.z + 0.5f * fmaxf((v[6] - mu) * rs * gm1[2] + be1[2], 0.f);
            o1.w = xo1.w + 0.5f * fmaxf((v[7] - mu) * rs * gm1[3] + be1[3], 0.f);
            *reinterpret_cast<float4*>(&xout[(size_t)row * HID + c0]) = o0;
            *reinterpret_cast<float4*>(&xout[(size_t)row * HID + c1]) = o1;
        }
    }
}

// ------------------------------------------------------------------
// head: out = relu(x @ wh1 + bh1) @ wh2 + bh2   (fused; shfl for 64->1)
// ------------------------------------------------------------------
__global__ __launch_bounds__(256) void head_kernel(
    const float* __restrict__ xin,
    const float* __restrict__ wh1, const float* __restrict__ bh1,
    const float* __restrict__ wh2, const float* __restrict__ bh2,
    float* __restrict__ out)
{
    __shared__ float As[64 * 32];   // 8 KB
    __shared__ float Bs[32 * 64];   // 8 KB
    int tid = threadIdx.x;
    int tx = tid & 15, ty = tid >> 4;
    int row0 = blockIdx.x * 64;

    u64 acc2[4][2];
#pragma unroll
    for (int i = 0; i < 4; i++) { acc2[i][0] = 0ull; acc2[i][1] = 0ull; }

    for (int kt = 0; kt < 4; kt++) {
        int kg0 = kt * 32;
#pragma unroll
        for (int p = 0; p < 8; p++) {
            int idx = tid + p * 256;
            int r = idx >> 5, k = idx & 31;
            int row = row0 + r;
            As[r * 32 + k] = (row < N_NODES) ? xin[(size_t)row * HID + kg0 + k] : 0.f;
        }
#pragma unroll
        for (int p = 0; p < 8; p++) {
            int idx = tid + p * 256;
            int k = idx >> 6, c = idx & 63;
            Bs[k * 64 + c] = wh1[(kg0 + k) * 64 + c];
        }
        __syncthreads();
#pragma unroll
        for (int kp = 0; kp < 16; kp++) {
            int k0 = kp * 2;
            float2 af[4];
#pragma unroll
            for (int i = 0; i < 4; i++)
                af[i] = *reinterpret_cast<const float2*>(&As[(ty * 4 + i) * 32 + k0]);
#pragma unroll
            for (int kk = 0; kk < 2; kk++) {
                int k = k0 + kk;
                float2 blv = *reinterpret_cast<const float2*>(&Bs[k * 64 + tx * 2]);
                float2 bhv = *reinterpret_cast<const float2*>(&Bs[k * 64 + 32 + tx * 2]);
                u64 b2[2];
                PACK2(b2[0], blv.x, bhv.x);
                PACK2(b2[1], blv.y, bhv.y);
                u64 a2[4];
#pragma unroll
                for (int i = 0; i < 4; i++)
                    PACK_DUP(a2[i], (kk == 0) ? af[i].x : af[i].y);
#pragma unroll
                for (int i = 0; i < 4; i++) {
                    FMA2(acc2[i][0], a2[i], b2[0]);
                    FMA2(acc2[i][1], a2[i], b2[1]);
                }
            }
        }
        __syncthreads();
    }

    // cols owned: {2tx, 2tx+1, 32+2tx, 32+2tx+1}
    float b1v[4], w2v[4];
#pragma unroll
    for (int j = 0; j < 2; j++) {
        b1v[j]     = bh1[tx * 2 + j];      w2v[j]     = wh2[tx * 2 + j];
        b1v[2 + j] = bh1[32 + tx * 2 + j]; w2v[2 + j] = wh2[32 + tx * 2 + j];
    }
    float bo = bh2[0];
#pragma unroll
    for (int i = 0; i < 4; i++) {
        float vv[4];
        UNPACK2(vv[0], vv[2], acc2[i][0]);
        UNPACK2(vv[1], vv[3], acc2[i][1]);
        float p = 0.f;
#pragma unroll
        for (int j = 0; j < 4; j++)
            p += fmaxf(vv[j] + b1v[j], 0.f) * w2v[j];
#pragma unroll
        for (int m = 8; m > 0; m >>= 1)
            p += __shfl_xor_sync(0xffffffffu, p, m);
        int row = row0 + ty * 4 + i;
        if (tx == 0 && row < N_NODES) out[row] = p + bo;
    }
}

// ------------------------------------------------------------------
extern "C" void kernel_launch(void* const* d_in, const int* in_sizes, int n_in,
                              void* d_out, int out_size)
{
    const float* x_num = (const float*)d_in[0];
    const int*   x_cat = (const int*)d_in[1];
    const int*   edge  = (const int*)d_in[2];
    const float* emb0  = (const float*)d_in[3];
    const float* emb1  = (const float*)d_in[4];
    const float* emb2  = (const float*)d_in[5];
    const float* emb3  = (const float*)d_in[6];
    const float* w_in  = (const float*)d_in[7];
    const float* b_in  = (const float*)d_in[8];
    const float* w1l   = (const float*)d_in[9];
    const float* b1l   = (const float*)d_in[10];
    const float* w1r   = (const float*)d_in[11];
    const float* w2l   = (const float*)d_in[12];
    const float* b2l   = (const float*)d_in[13];
    const float* w2r   = (const float*)d_in[14];
    const float* g1    = (const float*)d_in[15];
    const float* be1   = (const float*)d_in[16];
    const float* g2    = (const float*)d_in[17];
    const float* be2   = (const float*)d_in[18];
    const float* wh1   = (const float*)d_in[19];
    const float* bh1   = (const float*)d_in[20];
    const float* wh2   = (const float*)d_in[21];
    const float* bh2   = (const float*)d_in[22];
    float* out = (float*)d_out;

    int E = in_sizes[2] / 2;
    const int* src = edge;
    const int* dst = edge + E;

    int node_blocks32 = (N_NODES + 31) / 32;
    int node_blocks64 = (N_NODES + 63) / 64;
    int eblocks = (E + 255) / 256;

    // device-global ping-pong buffers
    float *xA, *xB;
    cudaGetSymbolAddress((void**)&xA, g_xA);
    cudaGetSymbolAddress((void**)&xB, g_xB);

    // CSR build (edge structure only)
    zero_deg_kernel<<<NB_SCAN, 256>>>();
    hist_kernel<<<eblocks, 256>>>(dst, E);
    scan1_kernel<<<NB_SCAN, 256>>>();
    scan2_kernel<<<1, 512>>>();
    scan3_kernel<<<NB_SCAN, 256>>>(E);
    fill_kernel<<<eblocks, 256>>>(src, dst, E);

    // input MLP -> xA
    input_kernel<<<node_blocks32, 128>>>(x_num, x_cat, emb0, emb1, emb2, emb3, w_in, b_in, xA);

    // layer 1: xA -> xB ; layer 2: xB -> xA  (gather fused, ping-pong)
    sage_kernel<<<node_blocks64, 256>>>(xA, xB, w1l, b1l, w1r, g1, be1);
    sage_kernel<<<node_blocks64, 256>>>(xB, xA, w2l, b2l, w2r, g2, be2);

    head_kernel<<<node_blocks64, 256>>>(xA, wh1, bh1, wh2, bh2, out);
}

// round 12
// speedup vs baseline: 1.2013x; 1.0782x over previous
#include <cuda_runtime.h>

#define N_NODES 100000
#define E_MAX   1600000
#define HID 128
#define NUM_IN 32
#define IN_DIM 71
#define LN_EPS 1e-5f
#define NB_SCAN ((N_NODES + 255) / 256)   // 391

// ---- packed fp32x2 helpers (sm_103a FFMA2: full fp32 precision, 2x rate) ----
#define FMA2(acc, a, b) \
    asm("fma.rn.f32x2 %0, %1, %2, %0;" : "+l"(acc) : "l"(a), "l"(b))
#define PACK_DUP(dst, x) do { \
    unsigned int _u = __float_as_uint(x); \
    asm("mov.b64 %0, {%1,%1};" : "=l"(dst) : "r"(_u)); } while (0)
#define PACK2(dst, lo, hi) \
    asm("mov.b64 %0, {%1,%2};" : "=l"(dst) : "r"(__float_as_uint(lo)), "r"(__float_as_uint(hi)))
#define UNPACK2(lo, hi, v) do { \
    unsigned int _l, _h; \
    asm("mov.b64 {%0,%1}, %2;" : "=r"(_l), "=r"(_h) : "l"(v)); \
    lo = __uint_as_float(_l); hi = __uint_as_float(_h); } while (0)

// ---- cp.async helpers ----
#define CP_ASYNC16(smem_u32, gptr) \
    asm volatile("cp.async.cg.shared.global [%0], [%1], 16;" :: "r"(smem_u32), "l"(gptr))
#define CP_COMMIT() asm volatile("cp.async.commit_group;" ::: "memory")
#define CP_WAIT0()  asm volatile("cp.async.wait_group 0;" ::: "memory")

typedef unsigned long long u64;

// ---- scratch (device globals; no allocation allowed) ----
__device__ __align__(16) float g_xA[N_NODES * HID];   // ping
__device__ __align__(16) float g_xB[N_NODES * HID];   // pong
__device__ int g_deg[N_NODES];
__device__ int g_rowptr[N_NODES + 1];
__device__ int g_cursor[N_NODES];
__device__ int g_csr[E_MAX];                          // src ids grouped by dst
__device__ int g_bsum[512];
__device__ int g_boff[512];

// ------------------------------------------------------------------
// CSR build: zero deg -> histogram -> 2-level exclusive scan -> fill
// ------------------------------------------------------------------
__global__ void zero_deg_kernel() {
    int i = blockIdx.x * blockDim.x + threadIdx.x;
    if (i < N_NODES) g_deg[i] = 0;
}

__global__ void hist_kernel(const int* __restrict__ dst, int E) {
    int i = blockIdx.x * blockDim.x + threadIdx.x;
    if (i < E) atomicAdd(&g_deg[dst[i]], 1);
}

__global__ __launch_bounds__(256) void scan1_kernel() {
    int tid = threadIdx.x;
    int lane = tid & 31, wid = tid >> 5;
    int i = blockIdx.x * 256 + tid;
    int v = (i < N_NODES) ? g_deg[i] : 0;
    int x = v;
#pragma unroll
    for (int o = 1; o < 32; o <<= 1) {
        int y = __shfl_up_sync(0xffffffffu, x, o);
        if (lane >= o) x += y;
    }
    __shared__ int wsum[8];
    if (lane == 31) wsum[wid] = x;
    __syncthreads();
    if (tid == 0) {
        int run = 0;
#pragma unroll
        for (int w = 0; w < 8; w++) { int t = wsum[w]; wsum[w] = run; run += t; }
        g_bsum[blockIdx.x] = run;
    }
    __syncthreads();
    int excl = x - v + wsum[wid];
    if (i < N_NODES) g_rowptr[i] = excl;
}

__global__ __launch_bounds__(512) void scan2_kernel() {
    __shared__ int s[512];
    int tid = threadIdx.x;
    int v = (tid < NB_SCAN) ? g_bsum[tid] : 0;
    s[tid] = v;
    __syncthreads();
    for (int o = 1; o < 512; o <<= 1) {
        int t = (tid >= o) ? s[tid - o] : 0;
        __syncthreads();
        s[tid] += t;
        __syncthreads();
    }
    if (tid < NB_SCAN) g_boff[tid] = s[tid] - v;   // exclusive
}

__global__ void scan3_kernel(int E) {
    int i = blockIdx.x * blockDim.x + threadIdx.x;
    if (i < N_NODES) {
        int v = g_rowptr[i] + g_boff[blockIdx.x];
        g_rowptr[i] = v;
        g_cursor[i] = v;
    }
    if (i == 0) g_rowptr[N_NODES] = E;
}

__global__ void fill_kernel(const int* __restrict__ src, const int* __restrict__ dst, int E) {
    int i = blockIdx.x * blockDim.x + threadIdx.x;
    if (i < E) {
        int d = dst[i];
        int pos = atomicAdd(&g_cursor[d], 1);
        g_csr[pos] = src[i];
    }
}

// ------------------------------------------------------------------
// input: x = relu(concat(x_num, emb lookups) @ w_in + b_in)
// ------------------------------------------------------------------
__global__ __launch_bounds__(128) void input_kernel(
    const float* __restrict__ x_num, const int* __restrict__ x_cat,
    const float* __restrict__ emb0, const float* __restrict__ emb1,
    const float* __restrict__ emb2, const float* __restrict__ emb3,
    const float* __restrict__ w_in, const float* __restrict__ b_in,
    float* __restrict__ xout)
{
    __shared__ float ws[IN_DIM * HID];       // 36352 B
    __shared__ float insT[IN_DIM * 32];      // k-major: insT[k*32 + n], 9088 B
    int tid = threadIdx.x;
    for (int i = tid; i < IN_DIM * HID; i += 128) ws[i] = w_in[i];

    int node0 = blockIdx.x * 32;
    for (int i = tid; i < 32 * NUM_IN; i += 128) {
        int n = i / NUM_IN, k = i % NUM_IN;
        int node = node0 + n;
        insT[k * 32 + n] = (node < N_NODES) ? x_num[node * NUM_IN + k] : 0.f;
    }
    for (int i = tid; i < 32 * 39; i += 128) {
        int n = i / 39, j = i % 39;
        int node = node0 + n;
        float v = 0.f;
        if (node < N_NODES) {
            if (j < 10)      v = emb0[x_cat[node * 4 + 0] * 10 + j];
            else if (j < 16) v = emb1[x_cat[node * 4 + 1] * 6 + (j - 10)];
            else if (j < 21) v = emb2[x_cat[node * 4 + 2] * 5 + (j - 16)];
            else             v = emb3[x_cat[node * 4 + 3] * 18 + (j - 21)];
        }
        insT[(NUM_IN + j) * 32 + n] = v;
    }
    __syncthreads();

    u64 acc2[16];
#pragma unroll
    for (int p = 0; p < 16; p++) acc2[p] = 0ull;

    for (int k = 0; k < IN_DIM; k++) {
        float w = ws[k * HID + tid];
        u64 w2; PACK_DUP(w2, w);
        const u64* ip = reinterpret_cast<const u64*>(&insT[k * 32]);
#pragma unroll
        for (int p = 0; p < 16; p++) {
            u64 in2 = ip[p];
            FMA2(acc2[p], w2, in2);
        }
    }
    float b = b_in[tid];
#pragma unroll
    for (int p = 0; p < 16; p++) {
        float lo, hi;
        UNPACK2(lo, hi, acc2[p]);
        int n0 = node0 + 2 * p;
        if (n0 < N_NODES)     xout[(size_t)n0 * HID + tid]       = fmaxf(lo + b, 0.f);
        if (n0 + 1 < N_NODES) xout[(size_t)(n0 + 1) * HID + tid] = fmaxf(hi + b, 0.f);
    }
}

// ------------------------------------------------------------------
// SAGE update (gather + GEMM + LN fused), ping-pong safe.
// BM=64, BN=128, BK=16, 256 threads (16x16), 16 kt iterations.
// cp.async double-buffered staging: Bs[2] (8KB each), As[2] (4KB each).
// smem = 32K (sMean) + 8K (As x2) + 16K (Bs x2) = 56KB -> 4 blocks/SM.
// Gather: 8 LDG.128 in flight per warp; GEMM: conflict-free B loads.
// ------------------------------------------------------------------
__global__ __launch_bounds__(256) void sage_kernel(
    const float* __restrict__ xin, float* __restrict__ xout,
    const float* __restrict__ wl, const float* __restrict__ bl,
    const float* __restrict__ wr,
    const float* __restrict__ gam, const float* __restrict__ bet)
{
    __shared__ float sMean[64 * 128];     // 32 KB
    __shared__ float As[2][64 * 16];      // 8 KB  (xin tile, kt>=8)
    __shared__ float Bs[2][16 * 128];     // 16 KB

    int tid = threadIdx.x;
    int row0 = blockIdx.x * 64;
    int warp = tid >> 5, lane = tid & 31;
    const float4* x4 = reinterpret_cast<const float4*>(xin);

    // staging thread mapping
    int bk = tid >> 4;              // 0..15  (k within tile)
    int bc = (tid & 15) * 8;        // col base, 8 floats = 2x16B
    int ar = tid >> 2;              // 0..63  (row within tile)
    int aq = (tid & 3) * 4;         // 4-float quad within 16 k's

    // boundary block: pre-zero As so invalid rows contribute zeros
    if (row0 + 64 > N_NODES) {
#pragma unroll
        for (int p = 0; p < 8; p++) {
            As[0][tid + ((p & 3) * 256)] = 0.f;   // covers 1024 per buffer
            As[1][tid + ((p & 3) * 256)] = 0.f;
        }
    }

    // ---- issue staging for kt=0 (overlaps with the whole gather phase) ----
    {
        const float* wsrc = wl + bk * 128 + bc;     // kt=0: kg = bk
        unsigned int s0 = (unsigned int)__cvta_generic_to_shared(&Bs[0][bk * 128 + bc]);
        CP_ASYNC16(s0, wsrc);
        CP_ASYNC16(s0 + 16, wsrc + 4);
        CP_COMMIT();
    }

    // ---- phase 1: gather mean (warp per row, 8 rows per warp) ----
#pragma unroll 1
    for (int j = 0; j < 8; j++) {
        int r = warp * 8 + j;
        int row = row0 + r;
        int beg = 0, end = 0;
        if (row < N_NODES) { beg = g_rowptr[row]; end = g_rowptr[row + 1]; }
        float4 a0 = make_float4(0.f, 0.f, 0.f, 0.f);
        float4 a1 = a0, a2 = a0, a3 = a0;
        int e = beg;
#pragma unroll 1
        for (; e + 8 <= end; e += 8) {
            int s0 = __ldg(&g_csr[e]);
            int s1 = __ldg(&g_csr[e + 1]);
            int s2 = __ldg(&g_csr[e + 2]);
            int s3 = __ldg(&g_csr[e + 3]);
            int s4 = __ldg(&g_csr[e + 4]);
            int s5 = __ldg(&g_csr[e + 5]);
            int s6 = __ldg(&g_csr[e + 6]);
            int s7 = __ldg(&g_csr[e + 7]);
            float4 v0 = x4[(size_t)s0 * 32 + lane];
            float4 v1 = x4[(size_t)s1 * 32 + lane];
            float4 v2 = x4[(size_t)s2 * 32 + lane];
            float4 v3 = x4[(size_t)s3 * 32 + lane];
            float4 v4 = x4[(size_t)s4 * 32 + lane];
            float4 v5 = x4[(size_t)s5 * 32 + lane];
            float4 v6 = x4[(size_t)s6 * 32 + lane];
            float4 v7 = x4[(size_t)s7 * 32 + lane];
            a0.x += v0.x; a0.y += v0.y; a0.z += v0.z; a0.w += v0.w;
            a1.x += v1.x; a1.y += v1.y; a1.z += v1.z; a1.w += v1.w;
            a2.x += v2.x; a2.y += v2.y; a2.z += v2.z; a2.w += v2.w;
            a3.x += v3.x; a3.y += v3.y; a3.z += v3.z; a3.w += v3.w;
            a0.x += v4.x; a0.y += v4.y; a0.z += v4.z; a0.w += v4.w;
            a1.x += v5.x; a1.y += v5.y; a1.z += v5.z; a1.w += v5.w;
            a2.x += v6.x; a2.y += v6.y; a2.z += v6.z; a2.w += v6.w;
            a3.x += v7.x; a3.y += v7.y; a3.z += v7.z; a3.w += v7.w;
        }
        if (e + 4 <= end) {
            int s0 = __ldg(&g_csr[e]);
            int s1 = __ldg(&g_csr[e + 1]);
            int s2 = __ldg(&g_csr[e + 2]);
            int s3 = __ldg(&g_csr[e + 3]);
            float4 v0 = x4[(size_t)s0 * 32 + lane];
            float4 v1 = x4[(size_t)s1 * 32 + lane];
            float4 v2 = x4[(size_t)s2 * 32 + lane];
            float4 v3 = x4[(size_t)s3 * 32 + lane];
            a0.x += v0.x; a0.y += v0.y; a0.z += v0.z; a0.w += v0.w;
            a1.x += v1.x; a1.y += v1.y; a1.z += v1.z; a1.w += v1.w;
            a2.x += v2.x; a2.y += v2.y; a2.z += v2.z; a2.w += v2.w;
            a3.x += v3.x; a3.y += v3.y; a3.z += v3.z; a3.w += v3.w;
            e += 4;
        }
        for (; e < end; e++) {
            int s = __ldg(&g_csr[e]);
            float4 v = x4[(size_t)s * 32 + lane];
            a0.x += v.x; a0.y += v.y; a0.z += v.z; a0.w += v.w;
        }
        float inv = 1.f / fmaxf((float)(end - beg), 1.f);
        float4 m;
        m.x = (a0.x + a1.x + a2.x + a3.x) * inv;
        m.y = (a0.y + a1.y + a2.y + a3.y) * inv;
        m.z = (a0.z + a1.z + a2.z + a3.z) * inv;
        m.w = (a0.w + a1.w + a2.w + a3.w) * inv;
        reinterpret_cast<float4*>(sMean)[r * 32 + lane] = m;
    }
    CP_WAIT0();
    __syncthreads();   // gather done + kt=0 staging visible

    // ---- phase 2: GEMM (double-buffered cp.async pipeline) ----
    int tx = tid & 15, ty = tid >> 4;
    u64 acc2[4][4];   // [row i][j]: lo = col 4tx+j, hi = col 64+4tx+j
#pragma unroll
    for (int i = 0; i < 4; i++)
#pragma unroll
        for (int j = 0; j < 4; j++) acc2[i][j] = 0ull;

#pragma unroll 1
    for (int kt = 0; kt < 16; kt++) {
        int buf = kt & 1;
        // stage kt+1 into the other buffer (async; overlapped with compute)
        if (kt < 15) {
            int nkt = kt + 1;
            int nbuf = nkt & 1;
            int kg0 = nkt * 16;
            const float* wsrc = (nkt < 8) ? (wl + kg0 * 128 + bk * 128 + bc)
                                          : (wr + (kg0 - 128) * 128 + bk * 128 + bc);
            unsigned int sb = (unsigned int)__cvta_generic_to_shared(&Bs[nbuf][bk * 128 + bc]);
            CP_ASYNC16(sb, wsrc);
            CP_ASYNC16(sb + 16, wsrc + 4);
            if (nkt >= 8) {
                int row = row0 + ar;
                if (row < N_NODES) {
                    unsigned int sa = (unsigned int)__cvta_generic_to_shared(&As[nbuf][ar * 16 + aq]);
                    CP_ASYNC16(sa, &xin[(size_t)row * HID + (kg0 - 128) + aq]);
                }
            }
            CP_COMMIT();
        }

        const float* Abase = (kt < 8) ? (sMean + kt * 16) : As[buf];
        int astr = (kt < 8) ? 128 : 16;
        const float* Bbase = Bs[buf];
#pragma unroll
        for (int kp = 0; kp < 8; kp++) {
            int k0 = kp * 2;
            float2 af[4];
#pragma unroll
            for (int i = 0; i < 4; i++)
                af[i] = *reinterpret_cast<const float2*>(&Abase[(ty * 4 + i) * astr + k0]);
            // ---- k = k0 ----
            {
                float4 blv = *reinterpret_cast<const float4*>(&Bbase[k0 * 128 + tx * 4]);
                float4 bhv = *reinterpret_cast<const float4*>(&Bbase[k0 * 128 + 64 + tx * 4]);
                u64 b2[4];
                PACK2(b2[0], blv.x, bhv.x);
                PACK2(b2[1], blv.y, bhv.y);
                PACK2(b2[2], blv.z, bhv.z);
                PACK2(b2[3], blv.w, bhv.w);
                u64 a2[4];
#pragma unroll
                for (int i = 0; i < 4; i++) PACK_DUP(a2[i], af[i].x);
#pragma unroll
                for (int i = 0; i < 4; i++)
#pragma unroll
                    for (int j = 0; j < 4; j++)
                        FMA2(acc2[i][j], a2[i], b2[j]);
            }
            // ---- k = k0 + 1 ----
            {
                float4 blv = *reinterpret_cast<const float4*>(&Bbase[(k0 + 1) * 128 + tx * 4]);
                float4 bhv = *reinterpret_cast<const float4*>(&Bbase[(k0 + 1) * 128 + 64 + tx * 4]);
                u64 b2[4];
                PACK2(b2[0], blv.x, bhv.x);
                PACK2(b2[1], blv.y, bhv.y);
                PACK2(b2[2], blv.z, bhv.z);
                PACK2(b2[3], blv.w, bhv.w);
                u64 a2[4];
#pragma unroll
                for (int i = 0; i < 4; i++) PACK_DUP(a2[i], af[i].y);
#pragma unroll
                for (int i = 0; i < 4; i++)
#pragma unroll
                    for (int j = 0; j < 4; j++)
                        FMA2(acc2[i][j], a2[i], b2[j]);
            }
        }
        if (kt < 15) {
            CP_WAIT0();
            __syncthreads();   // next buffer staged + this buffer free
        }
    }

    // epilogue: +bias, LayerNorm (16-lane shfl reduce), relu, residual
    int c0 = tx * 4;          // lo cols c0..c0+3
    int c1 = 64 + tx * 4;     // hi cols c1..c1+3
    float bl0[4], gm0[4], be0[4], bl1[4], gm1[4], be1[4];
#pragma unroll
    for (int j = 0; j < 4; j++) {
        bl0[j] = bl[c0 + j];  gm0[j] = gam[c0 + j];  be0[j] = bet[c0 + j];
        bl1[j] = bl[c1 + j];  gm1[j] = gam[c1 + j];  be1[j] = bet[c1 + j];
    }
#pragma unroll
    for (int i = 0; i < 4; i++) {
        int row = row0 + ty * 4 + i;
        float v[8];   // v[0..3] lo cols, v[4..7] hi cols
#pragma unroll
        for (int j = 0; j < 4; j++) {
            UNPACK2(v[j], v[4 + j], acc2[i][j]);
            v[j]     += bl0[j];
            v[4 + j] += bl1[j];
        }
        float s = 0.f, s2 = 0.f;
#pragma unroll
        for (int j = 0; j < 8; j++) { s += v[j]; s2 += v[j] * v[j]; }
#pragma unroll
        for (int m = 8; m > 0; m >>= 1) {
            s  += __shfl_xor_sync(0xffffffffu, s,  m);
            s2 += __shfl_xor_sync(0xffffffffu, s2, m);
        }
        float mu  = s * (1.f / 128.f);
        float var = s2 * (1.f / 128.f) - mu * mu;
        float rs  = rsqrtf(var + LN_EPS);
        if (row < N_NODES) {
            float4 xo0 = *reinterpret_cast<const float4*>(&xin[(size_t)row * HID + c0]);
            float4 xo1 = *reinterpret_cast<const float4*>(&xin[(size_t)row * HID + c1]);
            float4 o0, o1;
            o0.x = xo0.x + 0.5f * fmaxf((v[0] - mu) * rs * gm0[0] + be0[0], 0.f);
            o0.y = xo0.y + 0.5f * fmaxf((v[1] - mu) * rs * gm0[1] + be0[1], 0.f);
            o0.z = xo0.z + 0.5f * fmaxf((v[2] - mu) * rs * gm0[2] + be0[2], 0.f);
            o0.w = xo0.w + 0.5f * fmaxf((v[3] - mu) * rs * gm0[3] + be0[3], 0.f);
            o1.x = xo1.x + 0.5f * fmaxf((v[4] - mu) * rs * gm1[0] + be1[0], 0.f);
            o1.y = xo1.y + 0.5f * fmaxf((v[5] - mu) * rs * gm1[1] + be1[1], 0.f);
            o1.z = xo1.z + 0.5f * fmaxf((v[6] - mu) * rs * gm1[2] + be1[2], 0.f);
            o1.w = xo1.w + 0.5f * fmaxf((v[7] - mu) * rs * gm1[3] + be1[3], 0.f);
            *reinterpret_cast<float4*>(&xout[(size_t)row * HID + c0]) = o0;
            *reinterpret_cast<float4*>(&xout[(size_t)row * HID + c1]) = o1;
        }
    }
}

// ------------------------------------------------------------------
// head: out = relu(x @ wh1 + bh1) @ wh2 + bh2   (fused; shfl for 64->1)
// ------------------------------------------------------------------
__global__ __launch_bounds__(256) void head_kernel(
    const float* __restrict__ xin,
    const float* __restrict__ wh1, const float* __restrict__ bh1,
    const float* __restrict__ wh2, const float* __restrict__ bh2,
    float* __restrict__ out)
{
    __shared__ float As[64 * 32];   // 8 KB
    __shared__ float Bs[32 * 64];   // 8 KB
    int tid = threadIdx.x;
    int tx = tid & 15, ty = tid >> 4;
    int row0 = blockIdx.x * 64;

    u64 acc2[4][2];
#pragma unroll
    for (int i = 0; i < 4; i++) { acc2[i][0] = 0ull; acc2[i][1] = 0ull; }

    for (int kt = 0; kt < 4; kt++) {
        int kg0 = kt * 32;
#pragma unroll
        for (int p = 0; p < 8; p++) {
            int idx = tid + p * 256;
            int r = idx >> 5, k = idx & 31;
            int row = row0 + r;
            As[r * 32 + k] = (row < N_NODES) ? xin[(size_t)row * HID + kg0 + k] : 0.f;
        }
#pragma unroll
        for (int p = 0; p < 8; p++) {
            int idx = tid + p * 256;
            int k = idx >> 6, c = idx & 63;
            Bs[k * 64 + c] = wh1[(kg0 + k) * 64 + c];
        }
        __syncthreads();
#pragma unroll
        for (int kp = 0; kp < 16; kp++) {
            int k0 = kp * 2;
            float2 af[4];
#pragma unroll
            for (int i = 0; i < 4; i++)
                af[i] = *reinterpret_cast<const float2*>(&As[(ty * 4 + i) * 32 + k0]);
#pragma unroll
            for (int kk = 0; kk < 2; kk++) {
                int k = k0 + kk;
                float2 blv = *reinterpret_cast<const float2*>(&Bs[k * 64 + tx * 2]);
                float2 bhv = *reinterpret_cast<const float2*>(&Bs[k * 64 + 32 + tx * 2]);
                u64 b2[2];
                PACK2(b2[0], blv.x, bhv.x);
                PACK2(b2[1], blv.y, bhv.y);
                u64 a2[4];
#pragma unroll
                for (int i = 0; i < 4; i++)
                    PACK_DUP(a2[i], (kk == 0) ? af[i].x : af[i].y);
#pragma unroll
                for (int i = 0; i < 4; i++) {
                    FMA2(acc2[i][0], a2[i], b2[0]);
                    FMA2(acc2[i][1], a2[i], b2[1]);
                }
            }
        }
        __syncthreads();
    }

    // cols owned: {2tx, 2tx+1, 32+2tx, 32+2tx+1}
    float b1v[4], w2v[4];
#pragma unroll
    for (int j = 0; j < 2; j++) {
        b1v[j]     = bh1[tx * 2 + j];      w2v[j]     = wh2[tx * 2 + j];
        b1v[2 + j] = bh1[32 + tx * 2 + j]; w2v[2 + j] = wh2[32 + tx * 2 + j];
    }
    float bo = bh2[0];
#pragma unroll
    for (int i = 0; i < 4; i++) {
        float vv[4];
        UNPACK2(vv[0], vv[2], acc2[i][0]);
        UNPACK2(vv[1], vv[3], acc2[i][1]);
        float p = 0.f;
#pragma unroll
        for (int j = 0; j < 4; j++)
            p += fmaxf(vv[j] + b1v[j], 0.f) * w2v[j];
#pragma unroll
        for (int m = 8; m > 0; m >>= 1)
            p += __shfl_xor_sync(0xffffffffu, p, m);
        int row = row0 + ty * 4 + i;
        if (tx == 0 && row < N_NODES) out[row] = p + bo;
    }
}

// ------------------------------------------------------------------
extern "C" void kernel_launch(void* const* d_in, const int* in_sizes, int n_in,
                              void* d_out, int out_size)
{
    const float* x_num = (const float*)d_in[0];
    const int*   x_cat = (const int*)d_in[1];
    const int*   edge  = (const int*)d_in[2];
    const float* emb0  = (const float*)d_in[3];
    const float* emb1  = (const float*)d_in[4];
    const float* emb2  = (const float*)d_in[5];
    const float* emb3  = (const float*)d_in[6];
    const float* w_in  = (const float*)d_in[7];
    const float* b_in  = (const float*)d_in[8];
    const float* w1l   = (const float*)d_in[9];
    const float* b1l   = (const float*)d_in[10];
    const float* w1r   = (const float*)d_in[11];
    const float* w2l   = (const float*)d_in[12];
    const float* b2l   = (const float*)d_in[13];
    const float* w2r   = (const float*)d_in[14];
    const float* g1    = (const float*)d_in[15];
    const float* be1   = (const float*)d_in[16];
    const float* g2    = (const float*)d_in[17];
    const float* be2   = (const float*)d_in[18];
    const float* wh1   = (const float*)d_in[19];
    const float* bh1   = (const float*)d_in[20];
    const float* wh2   = (const float*)d_in[21];
    const float* bh2   = (const float*)d_in[22];
    float* out = (float*)d_out;

    int E = in_sizes[2] / 2;
    const int* src = edge;
    const int* dst = edge + E;

    int node_blocks32 = (N_NODES + 31) / 32;
    int node_blocks64 = (N_NODES + 63) / 64;
    int eblocks = (E + 255) / 256;

    // device-global ping-pong buffers
    float *xA, *xB;
    cudaGetSymbolAddress((void**)&xA, g_xA);
    cudaGetSymbolAddress((void**)&xB, g_xB);

    // CSR build (edge structure only)
    zero_deg_kernel<<<NB_SCAN, 256>>>();
    hist_kernel<<<eblocks, 256>>>(dst, E);
    scan1_kernel<<<NB_SCAN, 256>>>();
    scan2_kernel<<<1, 512>>>();
    scan3_kernel<<<NB_SCAN, 256>>>(E);
    fill_kernel<<<eblocks, 256>>>(src, dst, E);

    // input MLP -> xA
    input_kernel<<<node_blocks32, 128>>>(x_num, x_cat, emb0, emb1, emb2, emb3, w_in, b_in, xA);

    // layer 1: xA -> xB ; layer 2: xB -> xA  (gather fused, ping-pong)
    sage_kernel<<<node_blocks64, 256>>>(xA, xB, w1l, b1l, w1r, g1, be1);
    sage_kernel<<<node_blocks64, 256>>>(xB, xA, w2l, b2l, w2r, g2, be2);

    head_kernel<<<node_blocks64, 256>>>(xA, wh1, bh1, wh2, bh2, out);
}

// round 14
// speedup vs baseline: 1.2457x; 1.0369x over previous
#include <cuda_runtime.h>

#define N_NODES 100000
#define E_MAX   1600000
#define HID 128
#define NUM_IN 32
#define IN_DIM 71
#define LN_EPS 1e-5f
#define NB_SCAN ((N_NODES + 255) / 256)   // 391

// ---- packed fp32x2 helpers (sm_103a FFMA2: full fp32 precision, 2x rate) ----
#define FMA2(acc, a, b) \
    asm("fma.rn.f32x2 %0, %1, %2, %0;" : "+l"(acc) : "l"(a), "l"(b))
#define PACK_DUP(dst, x) do { \
    unsigned int _u = __float_as_uint(x); \
    asm("mov.b64 %0, {%1,%1};" : "=l"(dst) : "r"(_u)); } while (0)
#define PACK2(dst, lo, hi) \
    asm("mov.b64 %0, {%1,%2};" : "=l"(dst) : "r"(__float_as_uint(lo)), "r"(__float_as_uint(hi)))
#define UNPACK2(lo, hi, v) do { \
    unsigned int _l, _h; \
    asm("mov.b64 {%0,%1}, %2;" : "=r"(_l), "=r"(_h) : "l"(v)); \
    lo = __uint_as_float(_l); hi = __uint_as_float(_h); } while (0)

// ---- cp.async helpers ----
#define CP_ASYNC16(smem_u32, gptr) \
    asm volatile("cp.async.cg.shared.global [%0], [%1], 16;" :: "r"(smem_u32), "l"(gptr))
#define CP_COMMIT() asm volatile("cp.async.commit_group;" ::: "memory")
#define CP_WAIT0()  asm volatile("cp.async.wait_group 0;" ::: "memory")

typedef unsigned long long u64;

// ---- scratch (device globals; no allocation allowed) ----
__device__ __align__(16) float g_xA[N_NODES * HID];   // ping
__device__ __align__(16) float g_xB[N_NODES * HID];   // pong
__device__ int g_deg[N_NODES];
__device__ int g_rowptr[N_NODES + 1];
__device__ int g_cursor[N_NODES];
__device__ int g_csr[E_MAX];                          // src ids grouped by dst
__device__ int g_bsum[512];
__device__ int g_boff[512];

// ------------------------------------------------------------------
// CSR build: zero deg -> histogram -> 2-level exclusive scan -> fill
// ------------------------------------------------------------------
__global__ void zero_deg_kernel() {
    int i = blockIdx.x * blockDim.x + threadIdx.x;
    if (i < N_NODES) g_deg[i] = 0;
}

__global__ void hist_kernel(const int* __restrict__ dst, int E) {
    int i = blockIdx.x * blockDim.x + threadIdx.x;
    if (i < E) atomicAdd(&g_deg[dst[i]], 1);
}

__global__ __launch_bounds__(256) void scan1_kernel() {
    int tid = threadIdx.x;
    int lane = tid & 31, wid = tid >> 5;
    int i = blockIdx.x * 256 + tid;
    int v = (i < N_NODES) ? g_deg[i] : 0;
    int x = v;
#pragma unroll
    for (int o = 1; o < 32; o <<= 1) {
        int y = __shfl_up_sync(0xffffffffu, x, o);
        if (lane >= o) x += y;
    }
    __shared__ int wsum[8];
    if (lane == 31) wsum[wid] = x;
    __syncthreads();
    if (tid == 0) {
        int run = 0;
#pragma unroll
        for (int w = 0; w < 8; w++) { int t = wsum[w]; wsum[w] = run; run += t; }
        g_bsum[blockIdx.x] = run;
    }
    __syncthreads();
    int excl = x - v + wsum[wid];
    if (i < N_NODES) g_rowptr[i] = excl;
}

__global__ __launch_bounds__(512) void scan2_kernel() {
    __shared__ int s[512];
    int tid = threadIdx.x;
    int v = (tid < NB_SCAN) ? g_bsum[tid] : 0;
    s[tid] = v;
    __syncthreads();
    for (int o = 1; o < 512; o <<= 1) {
        int t = (tid >= o) ? s[tid - o] : 0;
        __syncthreads();
        s[tid] += t;
        __syncthreads();
    }
    if (tid < NB_SCAN) g_boff[tid] = s[tid] - v;   // exclusive
}

__global__ void scan3_kernel(int E) {
    int i = blockIdx.x * blockDim.x + threadIdx.x;
    if (i < N_NODES) {
        int v = g_rowptr[i] + g_boff[blockIdx.x];
        g_rowptr[i] = v;
        g_cursor[i] = v;
    }
    if (i == 0) g_rowptr[N_NODES] = E;
}

__global__ void fill_kernel(const int* __restrict__ src, const int* __restrict__ dst, int E) {
    int i = blockIdx.x * blockDim.x + threadIdx.x;
    if (i < E) {
        int d = dst[i];
        int pos = atomicAdd(&g_cursor[d], 1);
        g_csr[pos] = src[i];
    }
}

// ------------------------------------------------------------------
// input: x = relu(concat(x_num, emb lookups) @ w_in + b_in)
// w_in staged via cp.async (16B granules), overlapped with insT fill.
// ------------------------------------------------------------------
__global__ __launch_bounds__(128) void input_kernel(
    const float* __restrict__ x_num, const int* __restrict__ x_cat,
    const float* __restrict__ emb0, const float* __restrict__ emb1,
    const float* __restrict__ emb2, const float* __restrict__ emb3,
    const float* __restrict__ w_in, const float* __restrict__ b_in,
    float* __restrict__ xout)
{
    __shared__ float ws[IN_DIM * HID];       // 36352 B
    __shared__ float insT[IN_DIM * 32];      // k-major: insT[k*32 + n], 9088 B
    int tid = threadIdx.x;

    // async-stage w_in: 2272 x 16B, overlapped with the insT fill below
    for (int i = tid; i < IN_DIM * HID / 4; i += 128) {
        unsigned int s = (unsigned int)__cvta_generic_to_shared(&ws[i * 4]);
        CP_ASYNC16(s, w_in + i * 4);
    }
    CP_COMMIT();

    int node0 = blockIdx.x * 32;
    for (int i = tid; i < 32 * NUM_IN; i += 128) {
        int n = i / NUM_IN, k = i % NUM_IN;
        int node = node0 + n;
        insT[k * 32 + n] = (node < N_NODES) ? x_num[node * NUM_IN + k] : 0.f;
    }
    for (int i = tid; i < 32 * 39; i += 128) {
        int n = i / 39, j = i % 39;
        int node = node0 + n;
        float v = 0.f;
        if (node < N_NODES) {
            if (j < 10)      v = emb0[x_cat[node * 4 + 0] * 10 + j];
            else if (j < 16) v = emb1[x_cat[node * 4 + 1] * 6 + (j - 10)];
            else if (j < 21) v = emb2[x_cat[node * 4 + 2] * 5 + (j - 16)];
            else             v = emb3[x_cat[node * 4 + 3] * 18 + (j - 21)];
        }
        insT[(NUM_IN + j) * 32 + n] = v;
    }
    CP_WAIT0();
    __syncthreads();

    u64 acc2[16];
#pragma unroll
    for (int p = 0; p < 16; p++) acc2[p] = 0ull;

    for (int k = 0; k < IN_DIM; k++) {
        float w = ws[k * HID + tid];
        u64 w2; PACK_DUP(w2, w);
        const u64* ip = reinterpret_cast<const u64*>(&insT[k * 32]);
#pragma unroll
        for (int p = 0; p < 16; p++) {
            u64 in2 = ip[p];
            FMA2(acc2[p], w2, in2);
        }
    }
    float b = b_in[tid];
#pragma unroll
    for (int p = 0; p < 16; p++) {
        float lo, hi;
        UNPACK2(lo, hi, acc2[p]);
        int n0 = node0 + 2 * p;
        if (n0 < N_NODES)     xout[(size_t)n0 * HID + tid]       = fmaxf(lo + b, 0.f);
        if (n0 + 1 < N_NODES) xout[(size_t)(n0 + 1) * HID + tid] = fmaxf(hi + b, 0.f);
    }
}

// ------------------------------------------------------------------
// SAGE update (gather + GEMM + LN fused), ping-pong safe.
// BM=64, BN=128, BK=16, 256 threads (16x16), 16 kt iterations.
// cp.async double-buffered staging. smem = 56KB -> 4 blocks/SM.
// ------------------------------------------------------------------
__global__ __launch_bounds__(256) void sage_kernel(
    const float* __restrict__ xin, float* __restrict__ xout,
    const float* __restrict__ wl, const float* __restrict__ bl,
    const float* __restrict__ wr,
    const float* __restrict__ gam, const float* __restrict__ bet)
{
    __shared__ float sMean[64 * 128];     // 32 KB
    __shared__ float As[2][64 * 16];      // 8 KB  (xin tile, kt>=8)
    __shared__ float Bs[2][16 * 128];     // 16 KB

    int tid = threadIdx.x;
    int row0 = blockIdx.x * 64;
    int warp = tid >> 5, lane = tid & 31;
    const float4* x4 = reinterpret_cast<const float4*>(xin);

    // staging thread mapping
    int bk = tid >> 4;              // 0..15  (k within tile)
    int bc = (tid & 15) * 8;        // col base, 8 floats = 2x16B
    int ar = tid >> 2;              // 0..63  (row within tile)
    int aq = (tid & 3) * 4;         // 4-float quad within 16 k's

    // boundary block: pre-zero As so invalid rows contribute zeros
    // (safe: first As cp.async staging happens many barriers later, at kt=7)
    if (row0 + 64 > N_NODES) {
#pragma unroll
        for (int p = 0; p < 8; p++) {
            As[0][tid + ((p & 3) * 256)] = 0.f;
            As[1][tid + ((p & 3) * 256)] = 0.f;
        }
    }

    // ---- issue staging for kt=0 (overlaps with the whole gather phase) ----
    {
        const float* wsrc = wl + bk * 128 + bc;     // kt=0: kg = bk
        unsigned int s0 = (unsigned int)__cvta_generic_to_shared(&Bs[0][bk * 128 + bc]);
        CP_ASYNC16(s0, wsrc);
        CP_ASYNC16(s0 + 16, wsrc + 4);
        CP_COMMIT();
    }

    // ---- phase 1: gather mean (warp per row, 8 rows per warp) ----
#pragma unroll 1
    for (int j = 0; j < 8; j++) {
        int r = warp * 8 + j;
        int row = row0 + r;
        int beg = 0, end = 0;
        if (row < N_NODES) { beg = g_rowptr[row]; end = g_rowptr[row + 1]; }
        float4 a0 = make_float4(0.f, 0.f, 0.f, 0.f);
        float4 a1 = a0, a2 = a0, a3 = a0;
        int e = beg;
#pragma unroll 1
        for (; e + 8 <= end; e += 8) {
            int s0 = __ldg(&g_csr[e]);
            int s1 = __ldg(&g_csr[e + 1]);
            int s2 = __ldg(&g_csr[e + 2]);
            int s3 = __ldg(&g_csr[e + 3]);
            int s4 = __ldg(&g_csr[e + 4]);
            int s5 = __ldg(&g_csr[e + 5]);
            int s6 = __ldg(&g_csr[e + 6]);
            int s7 = __ldg(&g_csr[e + 7]);
            float4 v0 = x4[(size_t)s0 * 32 + lane];
            float4 v1 = x4[(size_t)s1 * 32 + lane];
            float4 v2 = x4[(size_t)s2 * 32 + lane];
            float4 v3 = x4[(size_t)s3 * 32 + lane];
            float4 v4 = x4[(size_t)s4 * 32 + lane];
            float4 v5 = x4[(size_t)s5 * 32 + lane];
            float4 v6 = x4[(size_t)s6 * 32 + lane];
            float4 v7 = x4[(size_t)s7 * 32 + lane];
            a0.x += v0.x; a0.y += v0.y; a0.z += v0.z; a0.w += v0.w;
            a1.x += v1.x; a1.y += v1.y; a1.z += v1.z; a1.w += v1.w;
            a2.x += v2.x; a2.y += v2.y; a2.z += v2.z; a2.w += v2.w;
            a3.x += v3.x; a3.y += v3.y; a3.z += v3.z; a3.w += v3.w;
            a0.x += v4.x; a0.y += v4.y; a0.z += v4.z; a0.w += v4.w;
            a1.x += v5.x; a1.y += v5.y; a1.z += v5.z; a1.w += v5.w;
            a2.x += v6.x; a2.y += v6.y; a2.z += v6.z; a2.w += v6.w;
            a3.x += v7.x; a3.y += v7.y; a3.z += v7.z; a3.w += v7.w;
        }
        if (e + 4 <= end) {
            int s0 = __ldg(&g_csr[e]);
            int s1 = __ldg(&g_csr[e + 1]);
            int s2 = __ldg(&g_csr[e + 2]);
            int s3 = __ldg(&g_csr[e + 3]);
            float4 v0 = x4[(size_t)s0 * 32 + lane];
            float4 v1 = x4[(size_t)s1 * 32 + lane];
            float4 v2 = x4[(size_t)s2 * 32 + lane];
            float4 v3 = x4[(size_t)s3 * 32 + lane];
            a0.x += v0.x; a0.y += v0.y; a0.z += v0.z; a0.w += v0.w;
            a1.x += v1.x; a1.y += v1.y; a1.z += v1.z; a1.w += v1.w;
            a2.x += v2.x; a2.y += v2.y; a2.z += v2.z; a2.w += v2.w;
            a3.x += v3.x; a3.y += v3.y; a3.z += v3.z; a3.w += v3.w;
            e += 4;
        }
        for (; e < end; e++) {
            int s = __ldg(&g_csr[e]);
            float4 v = x4[(size_t)s * 32 + lane];
            a0.x += v.x; a0.y += v.y; a0.z += v.z; a0.w += v.w;
        }
        float inv = 1.f / fmaxf((float)(end - beg), 1.f);
        float4 m;
        m.x = (a0.x + a1.x + a2.x + a3.x) * inv;
        m.y = (a0.y + a1.y + a2.y + a3.y) * inv;
        m.z = (a0.z + a1.z + a2.z + a3.z) * inv;
        m.w = (a0.w + a1.w + a2.w + a3.w) * inv;
        reinterpret_cast<float4*>(sMean)[r * 32 + lane] = m;
    }
    CP_WAIT0();
    __syncthreads();   // gather done + kt=0 staging visible

    // ---- phase 2: GEMM (double-buffered cp.async pipeline) ----
    int tx = tid & 15, ty = tid >> 4;
    u64 acc2[4][4];   // [row i][j]: lo = col 4tx+j, hi = col 64+4tx+j
#pragma unroll
    for (int i = 0; i < 4; i++)
#pragma unroll
        for (int j = 0; j < 4; j++) acc2[i][j] = 0ull;

#pragma unroll 1
    for (int kt = 0; kt < 16; kt++) {
        int buf = kt & 1;
        // stage kt+1 into the other buffer (async; overlapped with compute)
        if (kt < 15) {
            int nkt = kt + 1;
            int nbuf = nkt & 1;
            int kg0 = nkt * 16;
            const float* wsrc = (nkt < 8) ? (wl + kg0 * 128 + bk * 128 + bc)
                                          : (wr + (kg0 - 128) * 128 + bk * 128 + bc);
            unsigned int sb = (unsigned int)__cvta_generic_to_shared(&Bs[nbuf][bk * 128 + bc]);
            CP_ASYNC16(sb, wsrc);
            CP_ASYNC16(sb + 16, wsrc + 4);
            if (nkt >= 8) {
                int row = row0 + ar;
                if (row < N_NODES) {
                    unsigned int sa = (unsigned int)__cvta_generic_to_shared(&As[nbuf][ar * 16 + aq]);
                    CP_ASYNC16(sa, &xin[(size_t)row * HID + (kg0 - 128) + aq]);
                }
            }
            CP_COMMIT();
        }

        const float* Abase = (kt < 8) ? (sMean + kt * 16) : As[buf];
        int astr = (kt < 8) ? 128 : 16;
        const float* Bbase = Bs[buf];
#pragma unroll
        for (int kp = 0; kp < 8; kp++) {
            int k0 = kp * 2;
            float2 af[4];
#pragma unroll
            for (int i = 0; i < 4; i++)
                af[i] = *reinterpret_cast<const float2*>(&Abase[(ty * 4 + i) * astr + k0]);
            // ---- k = k0 ----
            {
                float4 blv = *reinterpret_cast<const float4*>(&Bbase[k0 * 128 + tx * 4]);
                float4 bhv = *reinterpret_cast<const float4*>(&Bbase[k0 * 128 + 64 + tx * 4]);
                u64 b2[4];
                PACK2(b2[0], blv.x, bhv.x);
                PACK2(b2[1], blv.y, bhv.y);
                PACK2(b2[2], blv.z, bhv.z);
                PACK2(b2[3], blv.w, bhv.w);
                u64 a2[4];
#pragma unroll
                for (int i = 0; i < 4; i++) PACK_DUP(a2[i], af[i].x);
#pragma unroll
                for (int i = 0; i < 4; i++)
#pragma unroll
                    for (int j = 0; j < 4; j++)
                        FMA2(acc2[i][j], a2[i], b2[j]);
            }
            // ---- k = k0 + 1 ----
            {
                float4 blv = *reinterpret_cast<const float4*>(&Bbase[(k0 + 1) * 128 + tx * 4]);
                float4 bhv = *reinterpret_cast<const float4*>(&Bbase[(k0 + 1) * 128 + 64 + tx * 4]);
                u64 b2[4];
                PACK2(b2[0], blv.x, bhv.x);
                PACK2(b2[1], blv.y, bhv.y);
                PACK2(b2[2], blv.z, bhv.z);
                PACK2(b2[3], blv.w, bhv.w);
                u64 a2[4];
#pragma unroll
                for (int i = 0; i < 4; i++) PACK_DUP(a2[i], af[i].y);
#pragma unroll
                for (int i = 0; i < 4; i++)
#pragma unroll
                    for (int j = 0; j < 4; j++)
                        FMA2(acc2[i][j], a2[i], b2[j]);
            }
        }
        if (kt < 15) {
            CP_WAIT0();
            __syncthreads();   // next buffer staged + this buffer free
        }
    }

    // epilogue: +bias, LayerNorm (16-lane shfl reduce), relu, residual
    int c0 = tx * 4;          // lo cols c0..c0+3
    int c1 = 64 + tx * 4;     // hi cols c1..c1+3
    float bl0[4], gm0[4], be0[4], bl1[4], gm1[4], be1[4];
#pragma unroll
    for (int j = 0; j < 4; j++) {
        bl0[j] = bl[c0 + j];  gm0[j] = gam[c0 + j];  be0[j] = bet[c0 + j];
        bl1[j] = bl[c1 + j];  gm1[j] = gam[c1 + j];  be1[j] = bet[c1 + j];
    }
#pragma unroll
    for (int i = 0; i < 4; i++) {
        int row = row0 + ty * 4 + i;
        float v[8];   // v[0..3] lo cols, v[4..7] hi cols
#pragma unroll
        for (int j = 0; j < 4; j++) {
            UNPACK2(v[j], v[4 + j], acc2[i][j]);
            v[j]     += bl0[j];
            v[4 + j] += bl1[j];
        }
        float s = 0.f, s2 = 0.f;
#pragma unroll
        for (int j = 0; j < 8; j++) { s += v[j]; s2 += v[j] * v[j]; }
#pragma unroll
        for (int m = 8; m > 0; m >>= 1) {
            s  += __shfl_xor_sync(0xffffffffu, s,  m);
            s2 += __shfl_xor_sync(0xffffffffu, s2, m);
        }
        float mu  = s * (1.f / 128.f);
        float var = s2 * (1.f / 128.f) - mu * mu;
        float rs  = rsqrtf(var + LN_EPS);
        if (row < N_NODES) {
            float4 xo0 = *reinterpret_cast<const float4*>(&xin[(size_t)row * HID + c0]);
            float4 xo1 = *reinterpret_cast<const float4*>(&xin[(size_t)row * HID + c1]);
            float4 o0, o1;
            o0.x = xo0.x + 0.5f * fmaxf((v[0] - mu) * rs * gm0[0] + be0[0], 0.f);
            o0.y = xo0.y + 0.5f * fmaxf((v[1] - mu) * rs * gm0[1] + be0[1], 0.f);
            o0.z = xo0.z + 0.5f * fmaxf((v[2] - mu) * rs * gm0[2] + be0[2], 0.f);
            o0.w = xo0.w + 0.5f * fmaxf((v[3] - mu) * rs * gm0[3] + be0[3], 0.f);
            o1.x = xo1.x + 0.5f * fmaxf((v[4] - mu) * rs * gm1[0] + be1[0], 0.f);
            o1.y = xo1.y + 0.5f * fmaxf((v[5] - mu) * rs * gm1[1] + be1[1], 0.f);
            o1.z = xo1.z + 0.5f * fmaxf((v[6] - mu) * rs * gm1[2] + be1[2], 0.f);
            o1.w = xo1.w + 0.5f * fmaxf((v[7] - mu) * rs * gm1[3] + be1[3], 0.f);
            *reinterpret_cast<float4*>(&xout[(size_t)row * HID + c0]) = o0;
            *reinterpret_cast<float4*>(&xout[(size_t)row * HID + c1]) = o1;
        }
    }
}

// ------------------------------------------------------------------
// head: out = relu(x @ wh1 + bh1) @ wh2 + bh2   (fused; shfl for 64->1)
// cp.async double-buffered staging, BK=16, 8 kt iterations.
// ------------------------------------------------------------------
__global__ __launch_bounds__(256) void head_kernel(
    const float* __restrict__ xin,
    const float* __restrict__ wh1, const float* __restrict__ bh1,
    const float* __restrict__ wh2, const float* __restrict__ bh2,
    float* __restrict__ out)
{
    __shared__ float As[2][64 * 16];   // 8 KB
    __shared__ float Bs[2][16 * 64];   // 8 KB
    int tid = threadIdx.x;
    int tx = tid & 15, ty = tid >> 4;
    int row0 = blockIdx.x * 64;

    // staging mapping: one CP_ASYNC16 per thread per tile
    int ar = tid >> 2;              // 0..63 row
    int aq = (tid & 3) * 4;         // quad within 16 k's
    int bkk = tid >> 4;             // 0..15 k
    int bcc = (tid & 15) * 4;       // col quad

    // boundary block: pre-zero As, then BARRIER before any cp.async to As
    // (R12 bug: STS zeros raced with prologue cp.async writes)
    if (row0 + 64 > N_NODES) {
#pragma unroll
        for (int p = 0; p < 4; p++) {
            As[0][tid + p * 256] = 0.f;
            As[1][tid + p * 256] = 0.f;
        }
    }
    __syncthreads();   // order pre-zero before prologue staging

    // prologue: stage kt=0
    {
        unsigned int sb = (unsigned int)__cvta_generic_to_shared(&Bs[0][bkk * 64 + bcc]);
        CP_ASYNC16(sb, wh1 + bkk * 64 + bcc);
        int row = row0 + ar;
        if (row < N_NODES) {
            unsigned int sa = (unsigned int)__cvta_generic_to_shared(&As[0][ar * 16 + aq]);
            CP_ASYNC16(sa, &xin[(size_t)row * HID + aq]);
        }
        CP_COMMIT();
        CP_WAIT0();
    }
    __syncthreads();

    u64 acc2[4][2];
#pragma unroll
    for (int i = 0; i < 4; i++) { acc2[i][0] = 0ull; acc2[i][1] = 0ull; }

#pragma unroll 1
    for (int kt = 0; kt < 8; kt++) {
        int buf = kt & 1;
        if (kt < 7) {
            int nkt = kt + 1;
            int nbuf = nkt & 1;
            int kg0 = nkt * 16;
            unsigned int sb = (unsigned int)__cvta_generic_to_shared(&Bs[nbuf][bkk * 64 + bcc]);
            CP_ASYNC16(sb, wh1 + (kg0 + bkk) * 64 + bcc);
            int row = row0 + ar;
            if (row < N_NODES) {
                unsigned int sa = (unsigned int)__cvta_generic_to_shared(&As[nbuf][ar * 16 + aq]);
                CP_ASYNC16(sa, &xin[(size_t)row * HID + kg0 + aq]);
            }
            CP_COMMIT();
        }

        const float* Abase = As[buf];
        const float* Bbase = Bs[buf];
#pragma unroll
        for (int kp = 0; kp < 8; kp++) {
            int k0 = kp * 2;
            float2 af[4];
#pragma unroll
            for (int i = 0; i < 4; i++)
                af[i] = *reinterpret_cast<const float2*>(&Abase[(ty * 4 + i) * 16 + k0]);
#pragma unroll
            for (int kk = 0; kk < 2; kk++) {
                int k = k0 + kk;
                float2 blv = *reinterpret_cast<const float2*>(&Bbase[k * 64 + tx * 2]);
                float2 bhv = *reinterpret_cast<const float2*>(&Bbase[k * 64 + 32 + tx * 2]);
                u64 b2[2];
                PACK2(b2[0], blv.x, bhv.x);
                PACK2(b2[1], blv.y, bhv.y);
                u64 a2[4];
#pragma unroll
                for (int i = 0; i < 4; i++)
                    PACK_DUP(a2[i], (kk == 0) ? af[i].x : af[i].y);
#pragma unroll
                for (int i = 0; i < 4; i++) {
                    FMA2(acc2[i][0], a2[i], b2[0]);
                    FMA2(acc2[i][1], a2[i], b2[1]);
                }
            }
        }
        if (kt < 7) {
            CP_WAIT0();
            __syncthreads();
        }
    }

    // cols owned: {2tx, 2tx+1, 32+2tx, 32+2tx+1}
    float b1v[4], w2v[4];
#pragma unroll
    for (int j = 0; j < 2; j++) {
        b1v[j]     = bh1[tx * 2 + j];      w2v[j]     = wh2[tx * 2 + j];
        b1v[2 + j] = bh1[32 + tx * 2 + j]; w2v[2 + j] = wh2[32 + tx * 2 + j];
    }
    float bo = bh2[0];
#pragma unroll
    for (int i = 0; i < 4; i++) {
        float vv[4];
        UNPACK2(vv[0], vv[2], acc2[i][0]);
        UNPACK2(vv[1], vv[3], acc2[i][1]);
        float p = 0.f;
#pragma unroll
        for (int j = 0; j < 4; j++)
            p += fmaxf(vv[j] + b1v[j], 0.f) * w2v[j];
#pragma unroll
        for (int m = 8; m > 0; m >>= 1)
            p += __shfl_xor_sync(0xffffffffu, p, m);
        int row = row0 + ty * 4 + i;
        if (tx == 0 && row < N_NODES) out[row] = p + bo;
    }
}

// ------------------------------------------------------------------
extern "C" void kernel_launch(void* const* d_in, const int* in_sizes, int n_in,
                              void* d_out, int out_size)
{
    const float* x_num = (const float*)d_in[0];
    const int*   x_cat = (const int*)d_in[1];
    const int*   edge  = (const int*)d_in[2];
    const float* emb0  = (const float*)d_in[3];
    const float* emb1  = (const float*)d_in[4];
    const float* emb2  = (const float*)d_in[5];
    const float* emb3  = (const float*)d_in[6];
    const float* w_in  = (const float*)d_in[7];
    const float* b_in  = (const float*)d_in[8];
    const float* w1l   = (const float*)d_in[9];
    const float* b1l   = (const float*)d_in[10];
    const float* w1r   = (const float*)d_in[11];
    const float* w2l   = (const float*)d_in[12];
    const float* b2l   = (const float*)d_in[13];
    const float* w2r   = (const float*)d_in[14];
    const float* g1    = (const float*)d_in[15];
    const float* be1   = (const float*)d_in[16];
    const float* g2    = (const float*)d_in[17];
    const float* be2   = (const float*)d_in[18];
    const float* wh1   = (const float*)d_in[19];
    const float* bh1   = (const float*)d_in[20];
    const float* wh2   = (const float*)d_in[21];
    const float* bh2   = (const float*)d_in[22];
    float* out = (float*)d_out;

    int E = in_sizes[2] / 2;
    const int* src = edge;
    const int* dst = edge + E;

    int node_blocks32 = (N_NODES + 31) / 32;
    int node_blocks64 = (N_NODES + 63) / 64;
    int eblocks = (E + 255) / 256;

    // device-global ping-pong buffers
    float *xA, *xB;
    cudaGetSymbolAddress((void**)&xA, g_xA);
    cudaGetSymbolAddress((void**)&xB, g_xB);

    // CSR build (edge structure only)
    zero_deg_kernel<<<NB_SCAN, 256>>>();
    hist_kernel<<<eblocks, 256>>>(dst, E);
    scan1_kernel<<<NB_SCAN, 256>>>();
    scan2_kernel<<<1, 512>>>();
    scan3_kernel<<<NB_SCAN, 256>>>(E);
    fill_kernel<<<eblocks, 256>>>(src, dst, E);

    // input MLP -> xA
    input_kernel<<<node_blocks32, 128>>>(x_num, x_cat, emb0, emb1, emb2, emb3, w_in, b_in, xA);

    // layer 1: xA -> xB ; layer 2: xB -> xA  (gather fused, ping-pong)
    sage_kernel<<<node_blocks64, 256>>>(xA, xB, w1l, b1l, w1r, g1, be1);
    sage_kernel<<<node_blocks64, 256>>>(xB, xA, w2l, b2l, w2r, g2, be2);

    head_kernel<<<node_blocks64, 256>>>(xA, wh1, bh1, wh2, bh2, out);
}

// round 15
// speedup vs baseline: 1.2460x; 1.0003x over previous
#include <cuda_runtime.h>

#define N_NODES 100000
#define E_MAX   1600000
#define CSR_CAP (E_MAX + 4 * N_NODES)     // room for 4-alignment padding per node
#define HID 128
#define NUM_IN 32
#define IN_DIM 71
#define LN_EPS 1e-5f
#define NB_SCAN ((N_NODES + 255) / 256)   // 391

// ---- packed fp32x2 helpers (sm_103a FFMA2: full fp32 precision, 2x rate) ----
#define FMA2(acc, a, b) \
    asm("fma.rn.f32x2 %0, %1, %2, %0;" : "+l"(acc) : "l"(a), "l"(b))
#define PACK_DUP(dst, x) do { \
    unsigned int _u = __float_as_uint(x); \
    asm("mov.b64 %0, {%1,%1};" : "=l"(dst) : "r"(_u)); } while (0)
#define PACK2(dst, lo, hi) \
    asm("mov.b64 %0, {%1,%2};" : "=l"(dst) : "r"(__float_as_uint(lo)), "r"(__float_as_uint(hi)))
#define UNPACK2(lo, hi, v) do { \
    unsigned int _l, _h; \
    asm("mov.b64 {%0,%1}, %2;" : "=r"(_l), "=r"(_h) : "l"(v)); \
    lo = __uint_as_float(_l); hi = __uint_as_float(_h); } while (0)

// ---- cp.async helpers ----
#define CP_ASYNC16(smem_u32, gptr) \
    asm volatile("cp.async.cg.shared.global [%0], [%1], 16;" :: "r"(smem_u32), "l"(gptr))
#define CP_COMMIT() asm volatile("cp.async.commit_group;" ::: "memory")
#define CP_WAIT0()  asm volatile("cp.async.wait_group 0;" ::: "memory")

typedef unsigned long long u64;

// ---- scratch (device globals; no allocation allowed) ----
__device__ __align__(16) float g_xA[N_NODES * HID];   // ping
__device__ __align__(16) float g_xB[N_NODES * HID];   // pong
__device__ int g_deg[N_NODES];
__device__ int g_rowptr[N_NODES];                     // 16B-aligned region start per node
__device__ int g_cursor[N_NODES];
__device__ __align__(16) int g_csr[CSR_CAP];          // src ids grouped by dst (rows 4-aligned)
__device__ int g_ctr;                                 // running slot counter

// ------------------------------------------------------------------
// CSR build: zero -> histogram -> offsets (block scan + atomic base) -> fill
// ------------------------------------------------------------------
__global__ void zero_deg_kernel() {
    int i = blockIdx.x * blockDim.x + threadIdx.x;
    if (i < N_NODES) g_deg[i] = 0;
    if (i == 0) g_ctr = 0;
}

__global__ void hist_kernel(const int* __restrict__ dst, int E) {
    int i = blockIdx.x * blockDim.x + threadIdx.x;
    if (i < E) atomicAdd(&g_deg[dst[i]], 1);
}

// per-node slot = align4(deg); block-exclusive-scan; block base via atomicAdd.
// Regions are disjoint + 16B-aligned; ordering across blocks is irrelevant
// (gather uses beg+deg, fill uses cursor).
__global__ __launch_bounds__(256) void offsets_kernel() {
    int tid = threadIdx.x;
    int lane = tid & 31, wid = tid >> 5;
    int i = blockIdx.x * 256 + tid;
    int deg = (i < N_NODES) ? g_deg[i] : 0;
    int slot = (deg + 3) & ~3;
    int x = slot;
#pragma unroll
    for (int o = 1; o < 32; o <<= 1) {
        int y = __shfl_up_sync(0xffffffffu, x, o);
        if (lane >= o) x += y;
    }
    __shared__ int wsum[8];
    __shared__ int sbase;
    if (lane == 31) wsum[wid] = x;
    __syncthreads();
    if (tid == 0) {
        int run = 0;
#pragma unroll
        for (int w = 0; w < 8; w++) { int t = wsum[w]; wsum[w] = run; run += t; }
        sbase = atomicAdd(&g_ctr, run);
    }
    __syncthreads();
    int excl = x - slot + wsum[wid] + sbase;
    if (i < N_NODES) {
        g_rowptr[i] = excl;
        g_cursor[i] = excl;
    }
}

__global__ void fill_kernel(const int* __restrict__ src, const int* __restrict__ dst, int E) {
    int i = blockIdx.x * blockDim.x + threadIdx.x;
    if (i < E) {
        int d = dst[i];
        int pos = atomicAdd(&g_cursor[d], 1);
        g_csr[pos] = src[i];
    }
}

// ------------------------------------------------------------------
// input: x = relu(concat(x_num, emb lookups) @ w_in + b_in)
// w_in staged via cp.async (16B granules), overlapped with insT fill.
// ------------------------------------------------------------------
__global__ __launch_bounds__(128) void input_kernel(
    const float* __restrict__ x_num, const int* __restrict__ x_cat,
    const float* __restrict__ emb0, const float* __restrict__ emb1,
    const float* __restrict__ emb2, const float* __restrict__ emb3,
    const float* __restrict__ w_in, const float* __restrict__ b_in,
    float* __restrict__ xout)
{
    __shared__ float ws[IN_DIM * HID];       // 36352 B
    __shared__ float insT[IN_DIM * 32];      // k-major: insT[k*32 + n], 9088 B
    int tid = threadIdx.x;

    // async-stage w_in: 2272 x 16B, overlapped with the insT fill below
    for (int i = tid; i < IN_DIM * HID / 4; i += 128) {
        unsigned int s = (unsigned int)__cvta_generic_to_shared(&ws[i * 4]);
        CP_ASYNC16(s, w_in + i * 4);
    }
    CP_COMMIT();

    int node0 = blockIdx.x * 32;
    for (int i = tid; i < 32 * NUM_IN; i += 128) {
        int n = i / NUM_IN, k = i % NUM_IN;
        int node = node0 + n;
        insT[k * 32 + n] = (node < N_NODES) ? x_num[node * NUM_IN + k] : 0.f;
    }
    for (int i = tid; i < 32 * 39; i += 128) {
        int n = i / 39, j = i % 39;
        int node = node0 + n;
        float v = 0.f;
        if (node < N_NODES) {
            if (j < 10)      v = emb0[x_cat[node * 4 + 0] * 10 + j];
            else if (j < 16) v = emb1[x_cat[node * 4 + 1] * 6 + (j - 10)];
            else if (j < 21) v = emb2[x_cat[node * 4 + 2] * 5 + (j - 16)];
            else             v = emb3[x_cat[node * 4 + 3] * 18 + (j - 21)];
        }
        insT[(NUM_IN + j) * 32 + n] = v;
    }
    CP_WAIT0();
    __syncthreads();

    u64 acc2[16];
#pragma unroll
    for (int p = 0; p < 16; p++) acc2[p] = 0ull;

    for (int k = 0; k < IN_DIM; k++) {
        float w = ws[k * HID + tid];
        u64 w2; PACK_DUP(w2, w);
        const u64* ip = reinterpret_cast<const u64*>(&insT[k * 32]);
#pragma unroll
        for (int p = 0; p < 16; p++) {
            u64 in2 = ip[p];
            FMA2(acc2[p], w2, in2);
        }
    }
    float b = b_in[tid];
#pragma unroll
    for (int p = 0; p < 16; p++) {
        float lo, hi;
        UNPACK2(lo, hi, acc2[p]);
        int n0 = node0 + 2 * p;
        if (n0 < N_NODES)     xout[(size_t)n0 * HID + tid]       = fmaxf(lo + b, 0.f);
        if (n0 + 1 < N_NODES) xout[(size_t)(n0 + 1) * HID + tid] = fmaxf(hi + b, 0.f);
    }
}

// ------------------------------------------------------------------
// SAGE update (gather + GEMM + LN fused), ping-pong safe.
// BM=64, BN=128, BK=16, 256 threads (16x16), 16 kt iterations.
// cp.async double-buffered staging. smem = 56KB -> 4 blocks/SM.
// Gather: int4 csr index loads (rows 16B-aligned) + 8 LDG.128 in flight.
// ------------------------------------------------------------------
__global__ __launch_bounds__(256) void sage_kernel(
    const float* __restrict__ xin, float* __restrict__ xout,
    const float* __restrict__ wl, const float* __restrict__ bl,
    const float* __restrict__ wr,
    const float* __restrict__ gam, const float* __restrict__ bet)
{
    __shared__ float sMean[64 * 128];     // 32 KB
    __shared__ float As[2][64 * 16];      // 8 KB  (xin tile, kt>=8)
    __shared__ float Bs[2][16 * 128];     // 16 KB

    int tid = threadIdx.x;
    int row0 = blockIdx.x * 64;
    int warp = tid >> 5, lane = tid & 31;
    const float4* x4 = reinterpret_cast<const float4*>(xin);

    // staging thread mapping
    int bk = tid >> 4;              // 0..15  (k within tile)
    int bc = (tid & 15) * 8;        // col base, 8 floats = 2x16B
    int ar = tid >> 2;              // 0..63  (row within tile)
    int aq = (tid & 3) * 4;         // 4-float quad within 16 k's

    // boundary block: pre-zero As so invalid rows contribute zeros
    // (safe: first As cp.async staging happens many barriers later, at kt=7)
    if (row0 + 64 > N_NODES) {
#pragma unroll
        for (int p = 0; p < 8; p++) {
            As[0][tid + ((p & 3) * 256)] = 0.f;
            As[1][tid + ((p & 3) * 256)] = 0.f;
        }
    }

    // ---- issue staging for kt=0 (overlaps with the whole gather phase) ----
    {
        const float* wsrc = wl + bk * 128 + bc;     // kt=0: kg = bk
        unsigned int s0 = (unsigned int)__cvta_generic_to_shared(&Bs[0][bk * 128 + bc]);
        CP_ASYNC16(s0, wsrc);
        CP_ASYNC16(s0 + 16, wsrc + 4);
        CP_COMMIT();
    }

    // ---- phase 1: gather mean (warp per row, 8 rows per warp) ----
#pragma unroll 1
    for (int j = 0; j < 8; j++) {
        int r = warp * 8 + j;
        int row = row0 + r;
        int beg = 0, cnt = 0;
        if (row < N_NODES) { beg = g_rowptr[row]; cnt = g_deg[row]; }
        int end = beg + cnt;
        float4 a0 = make_float4(0.f, 0.f, 0.f, 0.f);
        float4 a1 = a0, a2 = a0, a3 = a0;
        int e = beg;
#pragma unroll 1
        for (; e + 8 <= end; e += 8) {
            int4 q0 = *reinterpret_cast<const int4*>(&g_csr[e]);
            int4 q1 = *reinterpret_cast<const int4*>(&g_csr[e + 4]);
            float4 v0 = x4[(size_t)q0.x * 32 + lane];
            float4 v1 = x4[(size_t)q0.y * 32 + lane];
            float4 v2 = x4[(size_t)q0.z * 32 + lane];
            float4 v3 = x4[(size_t)q0.w * 32 + lane];
            float4 v4 = x4[(size_t)q1.x * 32 + lane];
            float4 v5 = x4[(size_t)q1.y * 32 + lane];
            float4 v6 = x4[(size_t)q1.z * 32 + lane];
            float4 v7 = x4[(size_t)q1.w * 32 + lane];
            a0.x += v0.x; a0.y += v0.y; a0.z += v0.z; a0.w += v0.w;
            a1.x += v1.x; a1.y += v1.y; a1.z += v1.z; a1.w += v1.w;
            a2.x += v2.x; a2.y += v2.y; a2.z += v2.z; a2.w += v2.w;
            a3.x += v3.x; a3.y += v3.y; a3.z += v3.z; a3.w += v3.w;
            a0.x += v4.x; a0.y += v4.y; a0.z += v4.z; a0.w += v4.w;
            a1.x += v5.x; a1.y += v5.y; a1.z += v5.z; a1.w += v5.w;
            a2.x += v6.x; a2.y += v6.y; a2.z += v6.z; a2.w += v6.w;
            a3.x += v7.x; a3.y += v7.y; a3.z += v7.z; a3.w += v7.w;
        }
        if (e + 4 <= end) {
            int4 q = *reinterpret_cast<const int4*>(&g_csr[e]);
            float4 v0 = x4[(size_t)q.x * 32 + lane];
            float4 v1 = x4[(size_t)q.y * 32 + lane];
            float4 v2 = x4[(size_t)q.z * 32 + lane];
            float4 v3 = x4[(size_t)q.w * 32 + lane];
            a0.x += v0.x; a0.y += v0.y; a0.z += v0.z; a0.w += v0.w;
            a1.x += v1.x; a1.y += v1.y; a1.z += v1.z; a1.w += v1.w;
            a2.x += v2.x; a2.y += v2.y; a2.z += v2.z; a2.w += v2.w;
            a3.x += v3.x; a3.y += v3.y; a3.z += v3.z; a3.w += v3.w;
            e += 4;
        }
        for (; e < end; e++) {
            int s = __ldg(&g_csr[e]);
            float4 v = x4[(size_t)s * 32 + lane];
            a0.x += v.x; a0.y += v.y; a0.z += v.z; a0.w += v.w;
        }
        float inv = 1.f / fmaxf((float)cnt, 1.f);
        float4 m;
        m.x = (a0.x + a1.x + a2.x + a3.x) * inv;
        m.y = (a0.y + a1.y + a2.y + a3.y) * inv;
        m.z = (a0.z + a1.z + a2.z + a3.z) * inv;
        m.w = (a0.w + a1.w + a2.w + a3.w) * inv;
        reinterpret_cast<float4*>(sMean)[r * 32 + lane] = m;
    }
    CP_WAIT0();
    __syncthreads();   // gather done + kt=0 staging visible

    // ---- phase 2: GEMM (double-buffered cp.async pipeline) ----
    int tx = tid & 15, ty = tid >> 4;
    u64 acc2[4][4];   // [row i][j]: lo = col 4tx+j, hi = col 64+4tx+j
#pragma unroll
    for (int i = 0; i < 4; i++)
#pragma unroll
        for (int j = 0; j < 4; j++) acc2[i][j] = 0ull;

#pragma unroll 1
    for (int kt = 0; kt < 16; kt++) {
        int buf = kt & 1;
        // stage kt+1 into the other buffer (async; overlapped with compute)
        if (kt < 15) {
            int nkt = kt + 1;
            int nbuf = nkt & 1;
            int kg0 = nkt * 16;
            const float* wsrc = (nkt < 8) ? (wl + kg0 * 128 + bk * 128 + bc)
                                          : (wr + (kg0 - 128) * 128 + bk * 128 + bc);
            unsigned int sb = (unsigned int)__cvta_generic_to_shared(&Bs[nbuf][bk * 128 + bc]);
            CP_ASYNC16(sb, wsrc);
            CP_ASYNC16(sb + 16, wsrc + 4);
            if (nkt >= 8) {
                int row = row0 + ar;
                if (row < N_NODES) {
                    unsigned int sa = (unsigned int)__cvta_generic_to_shared(&As[nbuf][ar * 16 + aq]);
                    CP_ASYNC16(sa, &xin[(size_t)row * HID + (kg0 - 128) + aq]);
                }
            }
            CP_COMMIT();
        }

        const float* Abase = (kt < 8) ? (sMean + kt * 16) : As[buf];
        int astr = (kt < 8) ? 128 : 16;
        const float* Bbase = Bs[buf];
#pragma unroll
        for (int kp = 0; kp < 8; kp++) {
            int k0 = kp * 2;
            float2 af[4];
#pragma unroll
            for (int i = 0; i < 4; i++)
                af[i] = *reinterpret_cast<const float2*>(&Abase[(ty * 4 + i) * astr + k0]);
            // ---- k = k0 ----
            {
                float4 blv = *reinterpret_cast<const float4*>(&Bbase[k0 * 128 + tx * 4]);
                float4 bhv = *reinterpret_cast<const float4*>(&Bbase[k0 * 128 + 64 + tx * 4]);
                u64 b2[4];
                PACK2(b2[0], blv.x, bhv.x);
                PACK2(b2[1], blv.y, bhv.y);
                PACK2(b2[2], blv.z, bhv.z);
                PACK2(b2[3], blv.w, bhv.w);
                u64 a2[4];
#pragma unroll
                for (int i = 0; i < 4; i++) PACK_DUP(a2[i], af[i].x);
#pragma unroll
                for (int i = 0; i < 4; i++)
#pragma unroll
                    for (int j = 0; j < 4; j++)
                        FMA2(acc2[i][j], a2[i], b2[j]);
            }
            // ---- k = k0 + 1 ----
            {
                float4 blv = *reinterpret_cast<const float4*>(&Bbase[(k0 + 1) * 128 + tx * 4]);
                float4 bhv = *reinterpret_cast<const float4*>(&Bbase[(k0 + 1) * 128 + 64 + tx * 4]);
                u64 b2[4];
                PACK2(b2[0], blv.x, bhv.x);
                PACK2(b2[1], blv.y, bhv.y);
                PACK2(b2[2], blv.z, bhv.z);
                PACK2(b2[3], blv.w, bhv.w);
                u64 a2[4];
#pragma unroll
                for (int i = 0; i < 4; i++) PACK_DUP(a2[i], af[i].y);
#pragma unroll
                for (int i = 0; i < 4; i++)
#pragma unroll
                    for (int j = 0; j < 4; j++)
                        FMA2(acc2[i][j], a2[i], b2[j]);
            }
        }
        if (kt < 15) {
            CP_WAIT0();
            __syncthreads();   // next buffer staged + this buffer free
        }
    }

    // epilogue: +bias, LayerNorm (16-lane shfl reduce), relu, residual
    int c0 = tx * 4;          // lo cols c0..c0+3
    int c1 = 64 + tx * 4;     // hi cols c1..c1+3
    float bl0[4], gm0[4], be0[4], bl1[4], gm1[4], be1[4];
#pragma unroll
    for (int j = 0; j < 4; j++) {
        bl0[j] = bl[c0 + j];  gm0[j] = gam[c0 + j];  be0[j] = bet[c0 + j];
        bl1[j] = bl[c1 + j];  gm1[j] = gam[c1 + j];  be1[j] = bet[c1 + j];
    }
#pragma unroll
    for (int i = 0; i < 4; i++) {
        int row = row0 + ty * 4 + i;
        float v[8];   // v[0..3] lo cols, v[4..7] hi cols
#pragma unroll
        for (int j = 0; j < 4; j++) {
            UNPACK2(v[j], v[4 + j], acc2[i][j]);
            v[j]     += bl0[j];
            v[4 + j] += bl1[j];
        }
        float s = 0.f, s2 = 0.f;
#pragma unroll
        for (int j = 0; j < 8; j++) { s += v[j]; s2 += v[j] * v[j]; }
#pragma unroll
        for (int m = 8; m > 0; m >>= 1) {
            s  += __shfl_xor_sync(0xffffffffu, s,  m);
            s2 += __shfl_xor_sync(0xffffffffu, s2, m);
        }
        float mu  = s * (1.f / 128.f);
        float var = s2 * (1.f / 128.f) - mu * mu;
        float rs  = rsqrtf(var + LN_EPS);
        if (row < N_NODES) {
            float4 xo0 = *reinterpret_cast<const float4*>(&xin[(size_t)row * HID + c0]);
            float4 xo1 = *reinterpret_cast<const float4*>(&xin[(size_t)row * HID + c1]);
            float4 o0, o1;
            o0.x = xo0.x + 0.5f * fmaxf((v[0] - mu) * rs * gm0[0] + be0[0], 0.f);
            o0.y = xo0.y + 0.5f * fmaxf((v[1] - mu) * rs * gm0[1] + be0[1], 0.f);
            o0.z = xo0.z + 0.5f * fmaxf((v[2] - mu) * rs * gm0[2] + be0[2], 0.f);
            o0.w = xo0.w + 0.5f * fmaxf((v[3] - mu) * rs * gm0[3] + be0[3], 0.f);
            o1.x = xo1.x + 0.5f * fmaxf((v[4] - mu) * rs * gm1[0] + be1[0], 0.f);
            o1.y = xo1.y + 0.5f * fmaxf((v[5] - mu) * rs * gm1[1] + be1[1], 0.f);
            o1.z = xo1.z + 0.5f * fmaxf((v[6] - mu) * rs * gm1[2] + be1[2], 0.f);
            o1.w = xo1.w + 0.5f * fmaxf((v[7] - mu) * rs * gm1[3] + be1[3], 0.f);
            *reinterpret_cast<float4*>(&xout[(size_t)row * HID + c0]) = o0;
            *reinterpret_cast<float4*>(&xout[(size_t)row * HID + c1]) = o1;
        }
    }
}

// ------------------------------------------------------------------
// head: out = relu(x @ wh1 + bh1) @ wh2 + bh2   (fused; shfl for 64->1)
// cp.async double-buffered staging, BK=16, 8 kt iterations.
// ------------------------------------------------------------------
__global__ __launch_bounds__(256) void head_kernel(
    const float* __restrict__ xin,
    const float* __restrict__ wh1, const float* __restrict__ bh1,
    const float* __restrict__ wh2, const float* __restrict__ bh2,
    float* __restrict__ out)
{
    __shared__ float As[2][64 * 16];   // 8 KB
    __shared__ float Bs[2][16 * 64];   // 8 KB
    int tid = threadIdx.x;
    int tx = tid & 15, ty = tid >> 4;
    int row0 = blockIdx.x * 64;

    // staging mapping: one CP_ASYNC16 per thread per tile
    int ar = tid >> 2;              // 0..63 row
    int aq = (tid & 3) * 4;         // quad within 16 k's
    int bkk = tid >> 4;             // 0..15 k
    int bcc = (tid & 15) * 4;       // col quad

    // boundary block: pre-zero As, then BARRIER before any cp.async to As
    if (row0 + 64 > N_NODES) {
#pragma unroll
        for (int p = 0; p < 4; p++) {
            As[0][tid + p * 256] = 0.f;
            As[1][tid + p * 256] = 0.f;
        }
    }
    __syncthreads();   // order pre-zero before prologue staging

    // prologue: stage kt=0
    {
        unsigned int sb = (unsigned int)__cvta_generic_to_shared(&Bs[0][bkk * 64 + bcc]);
        CP_ASYNC16(sb, wh1 + bkk * 64 + bcc);
        int row = row0 + ar;
        if (row < N_NODES) {
            unsigned int sa = (unsigned int)__cvta_generic_to_shared(&As[0][ar * 16 + aq]);
            CP_ASYNC16(sa, &xin[(size_t)row * HID + aq]);
        }
        CP_COMMIT();
        CP_WAIT0();
    }
    __syncthreads();

    u64 acc2[4][2];
#pragma unroll
    for (int i = 0; i < 4; i++) { acc2[i][0] = 0ull; acc2[i][1] = 0ull; }

#pragma unroll 1
    for (int kt = 0; kt < 8; kt++) {
        int buf = kt & 1;
        if (kt < 7) {
            int nkt = kt + 1;
            int nbuf = nkt & 1;
            int kg0 = nkt * 16;
            unsigned int sb = (unsigned int)__cvta_generic_to_shared(&Bs[nbuf][bkk * 64 + bcc]);
            CP_ASYNC16(sb, wh1 + (kg0 + bkk) * 64 + bcc);
            int row = row0 + ar;
            if (row < N_NODES) {
                unsigned int sa = (unsigned int)__cvta_generic_to_shared(&As[nbuf][ar * 16 + aq]);
                CP_ASYNC16(sa, &xin[(size_t)row * HID + kg0 + aq]);
            }
            CP_COMMIT();
        }

        const float* Abase = As[buf];
        const float* Bbase = Bs[buf];
#pragma unroll
        for (int kp = 0; kp < 8; kp++) {
            int k0 = kp * 2;
            float2 af[4];
#pragma unroll
            for (int i = 0; i < 4; i++)
                af[i] = *reinterpret_cast<const float2*>(&Abase[(ty * 4 + i) * 16 + k0]);
#pragma unroll
            for (int kk = 0; kk < 2; kk++) {
                int k = k0 + kk;
                float2 blv = *reinterpret_cast<const float2*>(&Bbase[k * 64 + tx * 2]);
                float2 bhv = *reinterpret_cast<const float2*>(&Bbase[k * 64 + 32 + tx * 2]);
                u64 b2[2];
                PACK2(b2[0], blv.x, bhv.x);
                PACK2(b2[1], blv.y, bhv.y);
                u64 a2[4];
#pragma unroll
                for (int i = 0; i < 4; i++)
                    PACK_DUP(a2[i], (kk == 0) ? af[i].x : af[i].y);
#pragma unroll
                for (int i = 0; i < 4; i++) {
                    FMA2(acc2[i][0], a2[i], b2[0]);
                    FMA2(acc2[i][1], a2[i], b2[1]);
                }
            }
        }
        if (kt < 7) {
            CP_WAIT0();
            __syncthreads();
        }
    }

    // cols owned: {2tx, 2tx+1, 32+2tx, 32+2tx+1}
    float b1v[4], w2v[4];
#pragma unroll
    for (int j = 0; j < 2; j++) {
        b1v[j]     = bh1[tx * 2 + j];      w2v[j]     = wh2[tx * 2 + j];
        b1v[2 + j] = bh1[32 + tx * 2 + j]; w2v[2 + j] = wh2[32 + tx * 2 + j];
    }
    float bo = bh2[0];
#pragma unroll
    for (int i = 0; i < 4; i++) {
        float vv[4];
        UNPACK2(vv[0], vv[2], acc2[i][0]);
        UNPACK2(vv[1], vv[3], acc2[i][1]);
        float p = 0.f;
#pragma unroll
        for (int j = 0; j < 4; j++)
            p += fmaxf(vv[j] + b1v[j], 0.f) * w2v[j];
#pragma unroll
        for (int m = 8; m > 0; m >>= 1)
            p += __shfl_xor_sync(0xffffffffu, p, m);
        int row = row0 + ty * 4 + i;
        if (tx == 0 && row < N_NODES) out[row] = p + bo;
    }
}

// ------------------------------------------------------------------
extern "C" void kernel_launch(void* const* d_in, const int* in_sizes, int n_in,
                              void* d_out, int out_size)
{
    const float* x_num = (const float*)d_in[0];
    const int*   x_cat = (const int*)d_in[1];
    const int*   edge  = (const int*)d_in[2];
    const float* emb0  = (const float*)d_in[3];
    const float* emb1  = (const float*)d_in[4];
    const float* emb2  = (const float*)d_in[5];
    const float* emb3  = (const float*)d_in[6];
    const float* w_in  = (const float*)d_in[7];
    const float* b_in  = (const float*)d_in[8];
    const float* w1l   = (const float*)d_in[9];
    const float* b1l   = (const float*)d_in[10];
    const float* w1r   = (const float*)d_in[11];
    const float* w2l   = (const float*)d_in[12];
    const float* b2l   = (const float*)d_in[13];
    const float* w2r   = (const float*)d_in[14];
    const float* g1    = (const float*)d_in[15];
    const float* be1   = (const float*)d_in[16];
    const float* g2    = (const float*)d_in[17];
    const float* be2   = (const float*)d_in[18];
    const float* wh1   = (const float*)d_in[19];
    const float* bh1   = (const float*)d_in[20];
    const float* wh2   = (const float*)d_in[21];
    const float* bh2   = (const float*)d_in[22];
    float* out = (float*)d_out;

    int E = in_sizes[2] / 2;
    const int* src = edge;
    const int* dst = edge + E;

    int node_blocks32 = (N_NODES + 31) / 32;
    int node_blocks64 = (N_NODES + 63) / 64;
    int eblocks = (E + 255) / 256;

    // device-global ping-pong buffers
    float *xA, *xB;
    cudaGetSymbolAddress((void**)&xA, g_xA);
    cudaGetSymbolAddress((void**)&xB, g_xB);

    // CSR build (4 kernels: zero -> hist -> offsets -> fill)
    zero_deg_kernel<<<NB_SCAN, 256>>>();
    hist_kernel<<<eblocks, 256>>>(dst, E);
    offsets_kernel<<<NB_SCAN, 256>>>();
    fill_kernel<<<eblocks, 256>>>(src, dst, E);

    // input MLP -> xA
    input_kernel<<<node_blocks32, 128>>>(x_num, x_cat, emb0, emb1, emb2, emb3, w_in, b_in, xA);

    // layer 1: xA -> xB ; layer 2: xB -> xA  (gather fused, ping-pong)
    sage_kernel<<<node_blocks64, 256>>>(xA, xB, w1l, b1l, w1r, g1, be1);
    sage_kernel<<<node_blocks64, 256>>>(xB, xA, w2l, b2l, w2r, g2, be2);

    head_kernel<<<node_blocks64, 256>>>(xA, wh1, bh1, wh2, bh2, out);
}